// round 4
// baseline (speedup 1.0000x reference)
#include <cuda_runtime.h>
#include <cuda_bf16.h>
#include <cstdint>

// Problem constants (fixed by the reference)
constexpr int Bb  = 4;
constexpr int Ss  = 2048;
constexpr int Dd  = 1024;
constexpr int Hh  = 16;
constexpr int DKk = 64;
constexpr int Mm  = Bb * Ss;          // 8192 rows

// ---------------------------------------------------------------------------
// Scratch (device globals — no runtime allocation allowed)
// ---------------------------------------------------------------------------
__device__ float g_q[(size_t)Mm * Dd];     // [B,S,D] layout, head-interleaved
__device__ float g_k[(size_t)Mm * Dd];
__device__ float g_v[(size_t)Mm * Dd];
__device__ float g_att[(size_t)Mm * Dd];   // attention output before O-proj

// ---------------------------------------------------------------------------
// SGEMM:  C[m][n] = sum_k A[m][k] * W[n][k] + bias[n]
// A: [M, 1024] row-major, W: [1024, 1024] row-major (n-major, k contiguous)
// Tiles: BM=128, BN=128, BK=8; 256 threads; 8x8 per-thread microtile.
// ---------------------------------------------------------------------------
constexpr int GN = 1024, GK = 1024;
constexpr int BM = 128, BN = 128, BK = 8;

__device__ __forceinline__ void gemm_body(
    const float* __restrict__ A, const float* __restrict__ W,
    const float* __restrict__ bias, float* __restrict__ C)
{
    __shared__ float As[BK][BM];
    __shared__ float Ws[BK][BN];

    const int tid = threadIdx.x;
    const int bm  = blockIdx.y * BM;
    const int bn  = blockIdx.x * BN;
    const int tx  = tid & 15;          // n-group
    const int ty  = tid >> 4;          // m-group
    const int lr  = tid >> 1;          // load row 0..127
    const int lc  = (tid & 1) * 4;     // load col 0 or 4

    const float* Ag = A + (size_t)(bm + lr) * GK + lc;
    const float* Wg = W + (size_t)(bn + lr) * GK + lc;

    float acc[8][8];
#pragma unroll
    for (int i = 0; i < 8; i++)
#pragma unroll
        for (int j = 0; j < 8; j++) acc[i][j] = 0.f;

    for (int k0 = 0; k0 < GK; k0 += BK) {
        const float4 a4 = *reinterpret_cast<const float4*>(Ag + k0);
        const float4 w4 = *reinterpret_cast<const float4*>(Wg + k0);
        As[lc + 0][lr] = a4.x; As[lc + 1][lr] = a4.y;
        As[lc + 2][lr] = a4.z; As[lc + 3][lr] = a4.w;
        Ws[lc + 0][lr] = w4.x; Ws[lc + 1][lr] = w4.y;
        Ws[lc + 2][lr] = w4.z; Ws[lc + 3][lr] = w4.w;
        __syncthreads();

#pragma unroll
        for (int d = 0; d < BK; d++) {
            const float4 a0 = *reinterpret_cast<const float4*>(&As[d][ty * 8]);
            const float4 a1 = *reinterpret_cast<const float4*>(&As[d][ty * 8 + 4]);
            const float4 b0 = *reinterpret_cast<const float4*>(&Ws[d][tx * 8]);
            const float4 b1 = *reinterpret_cast<const float4*>(&Ws[d][tx * 8 + 4]);
            const float af[8] = {a0.x, a0.y, a0.z, a0.w, a1.x, a1.y, a1.z, a1.w};
            const float bf[8] = {b0.x, b0.y, b0.z, b0.w, b1.x, b1.y, b1.z, b1.w};
#pragma unroll
            for (int i = 0; i < 8; i++)
#pragma unroll
                for (int j = 0; j < 8; j++)
                    acc[i][j] = fmaf(af[i], bf[j], acc[i][j]);
        }
        __syncthreads();
    }

    // epilogue: + bias, vectorized stores
#pragma unroll
    for (int i = 0; i < 8; i++) {
        const int m = bm + ty * 8 + i;
        const int n = bn + tx * 8;
        float* Cr = C + (size_t)m * GN + n;
        float4 o0, o1;
        o0.x = acc[i][0] + bias[n + 0];
        o0.y = acc[i][1] + bias[n + 1];
        o0.z = acc[i][2] + bias[n + 2];
        o0.w = acc[i][3] + bias[n + 3];
        o1.x = acc[i][4] + bias[n + 4];
        o1.y = acc[i][5] + bias[n + 5];
        o1.z = acc[i][6] + bias[n + 6];
        o1.w = acc[i][7] + bias[n + 7];
        *reinterpret_cast<float4*>(Cr)     = o0;
        *reinterpret_cast<float4*>(Cr + 4) = o1;
    }
}

__global__ __launch_bounds__(256)
void qkv_gemm(const float* __restrict__ x,
              const float* __restrict__ Wq, const float* __restrict__ bq,
              const float* __restrict__ Wk, const float* __restrict__ bk,
              const float* __restrict__ Wv, const float* __restrict__ bv)
{
    const float* W; const float* bias; float* C;
    if (blockIdx.z == 0)      { W = Wq; bias = bq; C = g_q; }
    else if (blockIdx.z == 1) { W = Wk; bias = bk; C = g_k; }
    else                      { W = Wv; bias = bv; C = g_v; }
    gemm_body(x, W, bias, C);
}

__global__ __launch_bounds__(256)
void out_gemm(const float* __restrict__ Wo, const float* __restrict__ bo,
              float* __restrict__ out)
{
    gemm_body(g_att, Wo, bo, out);
}

// ---------------------------------------------------------------------------
// Causal flash attention (fp32).
// Grid: (S/64, H, B). 256 threads. Per CTA: 64 q-rows of one (b,h).
// Streams 64-key tiles (kb <= qb), online softmax, P staged via smem.
// Thread (ty = tid/16, tx = tid%16) owns rows r0=ty*4..+3 and cols c0=tx*4..+3
// (cols = keys in the score phase, head-dims in the PV phase).
// ---------------------------------------------------------------------------
constexpr int BQ = 64, BKV = 64, PAD = 4;
constexpr int ATT_STRIDE = BQ + PAD;                 // 68 floats per smem row
constexpr size_t ATT_BUF  = (size_t)64 * ATT_STRIDE; // floats per buffer
constexpr size_t ATT_SMEM = 4 * ATT_BUF * sizeof(float); // 69632 bytes

__global__ __launch_bounds__(256)
void attn_kernel()
{
    extern __shared__ float sm[];
    float (*q_s)[ATT_STRIDE] = reinterpret_cast<float(*)[ATT_STRIDE]>(sm);
    float (*k_s)[ATT_STRIDE] = reinterpret_cast<float(*)[ATT_STRIDE]>(sm + ATT_BUF);
    float (*v_s)[ATT_STRIDE] = reinterpret_cast<float(*)[ATT_STRIDE]>(sm + 2 * ATT_BUF);
    float (*p_s)[ATT_STRIDE] = reinterpret_cast<float(*)[ATT_STRIDE]>(sm + 3 * ATT_BUF);

    const int tid = threadIdx.x;
    const int qb  = blockIdx.x;
    const int h   = blockIdx.y;
    const int b   = blockIdx.z;
    const int tx  = tid & 15;
    const int ty  = tid >> 4;
    const int r0  = ty * 4;
    const int c0  = tx * 4;
    const float scale = 0.125f;   // 1/sqrt(64)

    const size_t head_off = (size_t)b * Ss * Dd + (size_t)h * DKk;

    // Load Q tile transposed (q_s[d][r]) and pre-scaled.
    {
        const int r  = tid >> 2;               // 0..63
        const int d0 = (tid & 3) * 16;
        const float* qp = g_q + head_off + (size_t)(qb * BQ + r) * Dd + d0;
#pragma unroll
        for (int c = 0; c < 16; c += 4) {
            const float4 v = *reinterpret_cast<const float4*>(qp + c);
            q_s[d0 + c + 0][r] = v.x * scale;
            q_s[d0 + c + 1][r] = v.y * scale;
            q_s[d0 + c + 2][r] = v.z * scale;
            q_s[d0 + c + 3][r] = v.w * scale;
        }
    }

    float o[4][4];
    float m[4], l[4];
#pragma unroll
    for (int i = 0; i < 4; i++) {
        m[i] = -1e30f; l[i] = 0.f;
#pragma unroll
        for (int c = 0; c < 4; c++) o[i][c] = 0.f;
    }

    for (int kb = 0; kb <= qb; kb++) {
        __syncthreads();   // previous PV done reading k_s/v_s/p_s
        // Load K (transposed) and V (natural) tiles
        {
            const int r  = tid >> 2;
            const int d0 = (tid & 3) * 16;
            const float* kp = g_k + head_off + (size_t)(kb * BKV + r) * Dd + d0;
            const float* vp = g_v + head_off + (size_t)(kb * BKV + r) * Dd + d0;
#pragma unroll
            for (int c = 0; c < 16; c += 4) {
                const float4 kv = *reinterpret_cast<const float4*>(kp + c);
                k_s[d0 + c + 0][r] = kv.x;
                k_s[d0 + c + 1][r] = kv.y;
                k_s[d0 + c + 2][r] = kv.z;
                k_s[d0 + c + 3][r] = kv.w;
                const float4 vv = *reinterpret_cast<const float4*>(vp + c);
                *reinterpret_cast<float4*>(&v_s[r][d0 + c]) = vv;
            }
        }
        __syncthreads();

        // Scores: s[i][j] = (q_row r0+i) . (k_row c0+j), q pre-scaled
        float s[4][4];
#pragma unroll
        for (int i = 0; i < 4; i++)
#pragma unroll
            for (int j = 0; j < 4; j++) s[i][j] = 0.f;

#pragma unroll 8
        for (int d = 0; d < DKk; d++) {
            const float4 a = *reinterpret_cast<const float4*>(&q_s[d][r0]);
            const float4 k4 = *reinterpret_cast<const float4*>(&k_s[d][c0]);
            const float af[4] = {a.x, a.y, a.z, a.w};
            const float bf[4] = {k4.x, k4.y, k4.z, k4.w};
#pragma unroll
            for (int i = 0; i < 4; i++)
#pragma unroll
                for (int j = 0; j < 4; j++)
                    s[i][j] = fmaf(af[i], bf[j], s[i][j]);
        }

        // Causal mask on diagonal tile (key index > query index)
        if (kb == qb) {
#pragma unroll
            for (int i = 0; i < 4; i++)
#pragma unroll
                for (int j = 0; j < 4; j++)
                    if (c0 + j > r0 + i) s[i][j] = -1e30f;
        }

        // Online softmax per row (reduce across the 16 lanes sharing ty)
#pragma unroll
        for (int i = 0; i < 4; i++) {
            float mloc = fmaxf(fmaxf(s[i][0], s[i][1]), fmaxf(s[i][2], s[i][3]));
#pragma unroll
            for (int off = 8; off >= 1; off >>= 1)
                mloc = fmaxf(mloc, __shfl_xor_sync(0xffffffffu, mloc, off));
            const float mnew  = fmaxf(m[i], mloc);
            const float alpha = __expf(m[i] - mnew);
            float psum = 0.f;
#pragma unroll
            for (int j = 0; j < 4; j++) {
                const float p = __expf(s[i][j] - mnew);
                s[i][j] = p;
                psum += p;
            }
#pragma unroll
            for (int off = 8; off >= 1; off >>= 1)
                psum += __shfl_xor_sync(0xffffffffu, psum, off);
            l[i] = l[i] * alpha + psum;
            m[i] = mnew;
#pragma unroll
            for (int c = 0; c < 4; c++) o[i][c] *= alpha;
            *reinterpret_cast<float4*>(&p_s[r0 + i][c0]) =
                make_float4(s[i][0], s[i][1], s[i][2], s[i][3]);
        }
        __syncthreads();   // p_s visible; everyone done reading k_s

        // PV: o[i][c] += sum_j p_s[r0+i][j] * v_s[j][c0+c]
#pragma unroll 8
        for (int j = 0; j < BKV; j++) {
            float pv[4];
#pragma unroll
            for (int i = 0; i < 4; i++) pv[i] = p_s[r0 + i][j];
            const float4 v4 = *reinterpret_cast<const float4*>(&v_s[j][c0]);
            const float vf[4] = {v4.x, v4.y, v4.z, v4.w};
#pragma unroll
            for (int i = 0; i < 4; i++)
#pragma unroll
                for (int c = 0; c < 4; c++)
                    o[i][c] = fmaf(pv[i], vf[c], o[i][c]);
        }
    }

    // Normalize and write [B,S,D] layout
#pragma unroll
    for (int i = 0; i < 4; i++) {
        const float inv = 1.0f / l[i];
        float* op = g_att + head_off + (size_t)(qb * BQ + r0 + i) * Dd + c0;
        *reinterpret_cast<float4*>(op) =
            make_float4(o[i][0] * inv, o[i][1] * inv, o[i][2] * inv, o[i][3] * inv);
    }
}

// ---------------------------------------------------------------------------
// kernel_launch
// Inputs: 0:x 1:mask(ignored, causal is static) 2:Wq 3:bq 4:Wk 5:bk 6:Wv 7:bv 8:Wo 9:bo
// ---------------------------------------------------------------------------
extern "C" void kernel_launch(void* const* d_in, const int* in_sizes, int n_in,
                              void* d_out, int out_size)
{
    (void)in_sizes; (void)n_in; (void)out_size;
    const float* x  = (const float*)d_in[0];
    const float* Wq = (const float*)d_in[2];
    const float* bq = (const float*)d_in[3];
    const float* Wk = (const float*)d_in[4];
    const float* bk = (const float*)d_in[5];
    const float* Wv = (const float*)d_in[6];
    const float* bv = (const float*)d_in[7];
    const float* Wo = (const float*)d_in[8];
    const float* bo = (const float*)d_in[9];
    float* out = (float*)d_out;

    static bool attr_done = false;
    // Attribute set is idempotent and not a stream op; safe during capture.
    cudaFuncSetAttribute(attn_kernel,
                         cudaFuncAttributeMaxDynamicSharedMemorySize,
                         (int)ATT_SMEM);
    (void)attr_done;

    dim3 gemm_grid(GN / BN, Mm / BM, 3);
    qkv_gemm<<<gemm_grid, 256>>>(x, Wq, bq, Wk, bk, Wv, bv);

    dim3 attn_grid(Ss / BQ, Hh, Bb);
    attn_kernel<<<attn_grid, 256, ATT_SMEM>>>();

    dim3 out_grid(GN / BN, Mm / BM, 1);
    out_gemm<<<out_grid, 256>>>(Wo, bo, out);
}

// round 6
// speedup vs baseline: 1.3771x; 1.3771x over previous
#include <cuda_runtime.h>
#include <cuda_bf16.h>
#include <cstdint>

// Problem constants
constexpr int Bb  = 4;
constexpr int Ss  = 2048;
constexpr int Dd  = 1024;
constexpr int Hh  = 16;
constexpr int DKk = 64;
constexpr int Mm  = Bb * Ss;   // 8192
constexpr int KP  = 3072;      // 3 bf16 segments of 1024

// ---------------------------------------------------------------------------
// Scratch (device globals — no runtime allocation allowed)
// ---------------------------------------------------------------------------
__device__ float g_q[(size_t)Mm * Dd];
__device__ float g_k[(size_t)Mm * Dd];
__device__ float g_v[(size_t)Mm * Dd];
__device__ float g_att[(size_t)Mm * Dd];

// bf16x3 operand images, row-major, K' = 3072:
//   A-side segments: [hi | hi | lo]
//   W-side segments: [hi | lo | hi]
__device__ __nv_bfloat16 g_xa  [(size_t)Mm * KP];
__device__ __nv_bfloat16 g_atta[(size_t)Mm * KP];
__device__ __nv_bfloat16 g_wa  [(size_t)4 * 1024 * KP];

// ---------------------------------------------------------------------------
// Helpers
// ---------------------------------------------------------------------------
__device__ __forceinline__ uint32_t smem_u32(const void* p) {
    uint32_t a;
    asm("{ .reg .u64 t; cvta.to.shared.u64 t, %1; cvt.u32.u64 %0, t; }"
        : "=r"(a) : "l"(p));
    return a;
}

__device__ __forceinline__ void ldsm4(uint32_t* r, uint32_t addr) {
    asm volatile("ldmatrix.sync.aligned.m8n8.x4.shared.b16 {%0,%1,%2,%3}, [%4];"
        : "=r"(r[0]), "=r"(r[1]), "=r"(r[2]), "=r"(r[3]) : "r"(addr));
}

__device__ __forceinline__ void mma16816(float* c, const uint32_t* a,
                                         const uint32_t* b) {
    asm volatile(
        "mma.sync.aligned.m16n8k16.row.col.f32.bf16.bf16.f32 "
        "{%0,%1,%2,%3}, {%4,%5,%6,%7}, {%8,%9}, {%0,%1,%2,%3};"
        : "+f"(c[0]), "+f"(c[1]), "+f"(c[2]), "+f"(c[3])
        : "r"(a[0]), "r"(a[1]), "r"(a[2]), "r"(a[3]), "r"(b[0]), "r"(b[1]));
}

// fp32 -> (hi, lo) bf16 split of 8 values, packed as uint4 each
__device__ __forceinline__ void split8(const float* a, uint4& hv, uint4& lv) {
    unsigned short hs[8], ls[8];
#pragma unroll
    for (int j = 0; j < 8; j++) {
        __nv_bfloat16 h = __float2bfloat16(a[j]);
        float r = a[j] - __bfloat162float(h);
        __nv_bfloat16 l = __float2bfloat16(r);
        hs[j] = *reinterpret_cast<unsigned short*>(&h);
        ls[j] = *reinterpret_cast<unsigned short*>(&l);
    }
    hv.x = (uint32_t)hs[0] | ((uint32_t)hs[1] << 16);
    hv.y = (uint32_t)hs[2] | ((uint32_t)hs[3] << 16);
    hv.z = (uint32_t)hs[4] | ((uint32_t)hs[5] << 16);
    hv.w = (uint32_t)hs[6] | ((uint32_t)hs[7] << 16);
    lv.x = (uint32_t)ls[0] | ((uint32_t)ls[1] << 16);
    lv.y = (uint32_t)ls[2] | ((uint32_t)ls[3] << 16);
    lv.z = (uint32_t)ls[4] | ((uint32_t)ls[5] << 16);
    lv.w = (uint32_t)ls[6] | ((uint32_t)ls[7] << 16);
}

// ---------------------------------------------------------------------------
// Split kernels: fp32 [rows,1024] -> bf16 [rows,3072]
// ---------------------------------------------------------------------------
__device__ __forceinline__ void split_a_body(const float* __restrict__ src,
                                             __nv_bfloat16* __restrict__ dst) {
    const int idx = blockIdx.x * 256 + threadIdx.x;   // < 8192*128
    const int m  = idx >> 7;
    const int kk = (idx & 127) << 3;
    float a[8];
    const float4 f0 = *reinterpret_cast<const float4*>(src + (size_t)m * 1024 + kk);
    const float4 f1 = *reinterpret_cast<const float4*>(src + (size_t)m * 1024 + kk + 4);
    a[0]=f0.x; a[1]=f0.y; a[2]=f0.z; a[3]=f0.w;
    a[4]=f1.x; a[5]=f1.y; a[6]=f1.z; a[7]=f1.w;
    uint4 hv, lv; split8(a, hv, lv);
    __nv_bfloat16* row = dst + (size_t)m * KP;
    *reinterpret_cast<uint4*>(row + kk)        = hv;   // seg0 = hi
    *reinterpret_cast<uint4*>(row + 1024 + kk) = hv;   // seg1 = hi
    *reinterpret_cast<uint4*>(row + 2048 + kk) = lv;   // seg2 = lo
}

__global__ __launch_bounds__(256)
void split_x_kernel(const float* __restrict__ x) { split_a_body(x, g_xa); }

__global__ __launch_bounds__(256)
void split_att_kernel() { split_a_body(g_att, g_atta); }

__global__ __launch_bounds__(256)
void split_w_kernel(const float* __restrict__ Wq, const float* __restrict__ Wk,
                    const float* __restrict__ Wv, const float* __restrict__ Wo)
{
    const int idx = blockIdx.x * 256 + threadIdx.x;   // < 4*1024*128
    const int wi  = idx >> 17;
    const int rem = idx & 131071;
    const int n   = rem >> 7;
    const int kk  = (rem & 127) << 3;
    const float* W = (wi == 0) ? Wq : (wi == 1) ? Wk : (wi == 2) ? Wv : Wo;
    float a[8];
    const float4 f0 = *reinterpret_cast<const float4*>(W + (size_t)n * 1024 + kk);
    const float4 f1 = *reinterpret_cast<const float4*>(W + (size_t)n * 1024 + kk + 4);
    a[0]=f0.x; a[1]=f0.y; a[2]=f0.z; a[3]=f0.w;
    a[4]=f1.x; a[5]=f1.y; a[6]=f1.z; a[7]=f1.w;
    uint4 hv, lv; split8(a, hv, lv);
    __nv_bfloat16* row = g_wa + ((size_t)wi * 1024 + n) * KP;
    *reinterpret_cast<uint4*>(row + kk)        = hv;   // seg0 = hi
    *reinterpret_cast<uint4*>(row + 1024 + kk) = lv;   // seg1 = lo
    *reinterpret_cast<uint4*>(row + 2048 + kk) = hv;   // seg2 = hi
}

// ---------------------------------------------------------------------------
// bf16 HMMA GEMM: C[8192,1024] = A'[8192,3072] * W'[1024,3072]^T + bias
// CTA: 128x128 tile, BK=32, 256 threads = 8 warps (2x4), warp tile 64x32.
// Double-buffered smem (padded stride 40 bf16 -> conflict-free ldmatrix).
// ---------------------------------------------------------------------------
constexpr int SSTR = 40;   // smem row stride in bf16
constexpr int NIT  = KP / 32;   // 96

__device__ __forceinline__ void gemm_mma_body(
    const __nv_bfloat16* __restrict__ A,
    const __nv_bfloat16* __restrict__ B,
    const float* __restrict__ bias,
    float* __restrict__ out)
{
    __shared__ __nv_bfloat16 As[2][128][SSTR];
    __shared__ __nv_bfloat16 Bs[2][128][SSTR];

    const int tid  = threadIdx.x;
    const int lane = tid & 31;
    const int wid  = tid >> 5;
    const int wm   = (wid >> 2) * 64;   // 0 or 64
    const int wn   = (wid & 3) * 32;    // 0,32,64,96
    const int bm   = blockIdx.y * 128;
    const int bn   = blockIdx.x * 128;

    // gmem load mapping: each thread loads 16 bf16 (2x uint4) of one row
    const int lr  = tid >> 1;
    const int lcg = (tid & 1) * 16;
    const __nv_bfloat16* Ag = A + (size_t)(bm + lr) * KP + lcg;
    const __nv_bfloat16* Bg = B + (size_t)(bn + lr) * KP + lcg;

    float c[4][4][4];
#pragma unroll
    for (int mt = 0; mt < 4; mt++)
#pragma unroll
        for (int nt = 0; nt < 4; nt++)
#pragma unroll
            for (int i = 0; i < 4; i++) c[mt][nt][i] = 0.f;

    // preload iter 0
    uint4 la0 = *reinterpret_cast<const uint4*>(Ag);
    uint4 la1 = *reinterpret_cast<const uint4*>(Ag + 8);
    uint4 lb0 = *reinterpret_cast<const uint4*>(Bg);
    uint4 lb1 = *reinterpret_cast<const uint4*>(Bg + 8);
    *reinterpret_cast<uint4*>(&As[0][lr][lcg])     = la0;
    *reinterpret_cast<uint4*>(&As[0][lr][lcg + 8]) = la1;
    *reinterpret_cast<uint4*>(&Bs[0][lr][lcg])     = lb0;
    *reinterpret_cast<uint4*>(&Bs[0][lr][lcg + 8]) = lb1;
    __syncthreads();

    // ldmatrix lane addressing (precomputed pieces)
    const int a_r = (lane & 15);
    const int a_c = (lane >> 4) << 3;
    const int mat = lane >> 3;
    const int b_r = ((mat >> 1) << 3) + (lane & 7);
    const int b_c = (mat & 1) << 3;

    int cur = 0;
    for (int it = 0; it < NIT; it++) {
        if (it + 1 < NIT) {
            const int k0 = (it + 1) * 32;
            la0 = *reinterpret_cast<const uint4*>(Ag + k0);
            la1 = *reinterpret_cast<const uint4*>(Ag + k0 + 8);
            lb0 = *reinterpret_cast<const uint4*>(Bg + k0);
            lb1 = *reinterpret_cast<const uint4*>(Bg + k0 + 8);
        }

#pragma unroll
        for (int ks = 0; ks < 32; ks += 16) {
            uint32_t af[4][4];
#pragma unroll
            for (int mt = 0; mt < 4; mt++)
                ldsm4(af[mt], smem_u32(&As[cur][wm + mt * 16 + a_r][ks + a_c]));
            uint32_t bf[4][2];
#pragma unroll
            for (int p = 0; p < 2; p++) {
                uint32_t t[4];
                ldsm4(t, smem_u32(&Bs[cur][wn + p * 16 + b_r][ks + b_c]));
                bf[p * 2 + 0][0] = t[0]; bf[p * 2 + 0][1] = t[1];
                bf[p * 2 + 1][0] = t[2]; bf[p * 2 + 1][1] = t[3];
            }
#pragma unroll
            for (int mt = 0; mt < 4; mt++)
#pragma unroll
                for (int nt = 0; nt < 4; nt++)
                    mma16816(c[mt][nt], af[mt], bf[nt]);
        }

        if (it + 1 < NIT) {
            const int nb = cur ^ 1;
            *reinterpret_cast<uint4*>(&As[nb][lr][lcg])     = la0;
            *reinterpret_cast<uint4*>(&As[nb][lr][lcg + 8]) = la1;
            *reinterpret_cast<uint4*>(&Bs[nb][lr][lcg])     = lb0;
            *reinterpret_cast<uint4*>(&Bs[nb][lr][lcg + 8]) = lb1;
            __syncthreads();
            cur = nb;
        }
    }

    // epilogue: + bias, direct stores (float2 per fragment half)
#pragma unroll
    for (int nt = 0; nt < 4; nt++) {
        const int n0 = bn + wn + nt * 8 + (lane & 3) * 2;
        const float b0 = bias[n0], b1 = bias[n0 + 1];
#pragma unroll
        for (int mt = 0; mt < 4; mt++) {
            const int m0 = bm + wm + mt * 16 + (lane >> 2);
            float2 v0 = make_float2(c[mt][nt][0] + b0, c[mt][nt][1] + b1);
            float2 v1 = make_float2(c[mt][nt][2] + b0, c[mt][nt][3] + b1);
            *reinterpret_cast<float2*>(out + (size_t)m0 * 1024 + n0)       = v0;
            *reinterpret_cast<float2*>(out + (size_t)(m0 + 8) * 1024 + n0) = v1;
        }
    }
}

__global__ __launch_bounds__(256)
void gemm_qkv_mma(const float* __restrict__ bq, const float* __restrict__ bk,
                  const float* __restrict__ bv)
{
    const int w = blockIdx.z;
    const float* bias; float* outp;
    if (w == 0)      { bias = bq; outp = g_q; }
    else if (w == 1) { bias = bk; outp = g_k; }
    else             { bias = bv; outp = g_v; }
    gemm_mma_body(g_xa, g_wa + (size_t)w * 1024 * KP, bias, outp);
}

__global__ __launch_bounds__(256)
void gemm_o_mma(const float* __restrict__ bo, float* __restrict__ outp)
{
    gemm_mma_body(g_atta, g_wa + (size_t)3 * 1024 * KP, bo, outp);
}

// ---------------------------------------------------------------------------
// Causal flash attention (fp32 SIMT) — unchanged from R4 (proven correct)
// ---------------------------------------------------------------------------
constexpr int BQ = 64, BKV = 64, PAD = 4;
constexpr int ATT_STRIDE = BQ + PAD;
constexpr size_t ATT_BUF  = (size_t)64 * ATT_STRIDE;
constexpr size_t ATT_SMEM = 4 * ATT_BUF * sizeof(float);

__global__ __launch_bounds__(256)
void attn_kernel()
{
    extern __shared__ float sm[];
    float (*q_s)[ATT_STRIDE] = reinterpret_cast<float(*)[ATT_STRIDE]>(sm);
    float (*k_s)[ATT_STRIDE] = reinterpret_cast<float(*)[ATT_STRIDE]>(sm + ATT_BUF);
    float (*v_s)[ATT_STRIDE] = reinterpret_cast<float(*)[ATT_STRIDE]>(sm + 2 * ATT_BUF);
    float (*p_s)[ATT_STRIDE] = reinterpret_cast<float(*)[ATT_STRIDE]>(sm + 3 * ATT_BUF);

    const int tid = threadIdx.x;
    const int qb  = blockIdx.x;
    const int h   = blockIdx.y;
    const int b   = blockIdx.z;
    const int tx  = tid & 15;
    const int ty  = tid >> 4;
    const int r0  = ty * 4;
    const int c0  = tx * 4;
    const float scale = 0.125f;

    const size_t head_off = (size_t)b * Ss * Dd + (size_t)h * DKk;

    {
        const int r  = tid >> 2;
        const int d0 = (tid & 3) * 16;
        const float* qp = g_q + head_off + (size_t)(qb * BQ + r) * Dd + d0;
#pragma unroll
        for (int c = 0; c < 16; c += 4) {
            const float4 v = *reinterpret_cast<const float4*>(qp + c);
            q_s[d0 + c + 0][r] = v.x * scale;
            q_s[d0 + c + 1][r] = v.y * scale;
            q_s[d0 + c + 2][r] = v.z * scale;
            q_s[d0 + c + 3][r] = v.w * scale;
        }
    }

    float o[4][4];
    float m[4], l[4];
#pragma unroll
    for (int i = 0; i < 4; i++) {
        m[i] = -1e30f; l[i] = 0.f;
#pragma unroll
        for (int c = 0; c < 4; c++) o[i][c] = 0.f;
    }

    for (int kb = 0; kb <= qb; kb++) {
        __syncthreads();
        {
            const int r  = tid >> 2;
            const int d0 = (tid & 3) * 16;
            const float* kp = g_k + head_off + (size_t)(kb * BKV + r) * Dd + d0;
            const float* vp = g_v + head_off + (size_t)(kb * BKV + r) * Dd + d0;
#pragma unroll
            for (int c = 0; c < 16; c += 4) {
                const float4 kv = *reinterpret_cast<const float4*>(kp + c);
                k_s[d0 + c + 0][r] = kv.x;
                k_s[d0 + c + 1][r] = kv.y;
                k_s[d0 + c + 2][r] = kv.z;
                k_s[d0 + c + 3][r] = kv.w;
                const float4 vv = *reinterpret_cast<const float4*>(vp + c);
                *reinterpret_cast<float4*>(&v_s[r][d0 + c]) = vv;
            }
        }
        __syncthreads();

        float s[4][4];
#pragma unroll
        for (int i = 0; i < 4; i++)
#pragma unroll
            for (int j = 0; j < 4; j++) s[i][j] = 0.f;

#pragma unroll 8
        for (int d = 0; d < DKk; d++) {
            const float4 a = *reinterpret_cast<const float4*>(&q_s[d][r0]);
            const float4 k4 = *reinterpret_cast<const float4*>(&k_s[d][c0]);
            const float af[4] = {a.x, a.y, a.z, a.w};
            const float bfv[4] = {k4.x, k4.y, k4.z, k4.w};
#pragma unroll
            for (int i = 0; i < 4; i++)
#pragma unroll
                for (int j = 0; j < 4; j++)
                    s[i][j] = fmaf(af[i], bfv[j], s[i][j]);
        }

        if (kb == qb) {
#pragma unroll
            for (int i = 0; i < 4; i++)
#pragma unroll
                for (int j = 0; j < 4; j++)
                    if (c0 + j > r0 + i) s[i][j] = -1e30f;
        }

#pragma unroll
        for (int i = 0; i < 4; i++) {
            float mloc = fmaxf(fmaxf(s[i][0], s[i][1]), fmaxf(s[i][2], s[i][3]));
#pragma unroll
            for (int off = 8; off >= 1; off >>= 1)
                mloc = fmaxf(mloc, __shfl_xor_sync(0xffffffffu, mloc, off));
            const float mnew  = fmaxf(m[i], mloc);
            const float alpha = __expf(m[i] - mnew);
            float psum = 0.f;
#pragma unroll
            for (int j = 0; j < 4; j++) {
                const float p = __expf(s[i][j] - mnew);
                s[i][j] = p;
                psum += p;
            }
#pragma unroll
            for (int off = 8; off >= 1; off >>= 1)
                psum += __shfl_xor_sync(0xffffffffu, psum, off);
            l[i] = l[i] * alpha + psum;
            m[i] = mnew;
#pragma unroll
            for (int c = 0; c < 4; c++) o[i][c] *= alpha;
            *reinterpret_cast<float4*>(&p_s[r0 + i][c0]) =
                make_float4(s[i][0], s[i][1], s[i][2], s[i][3]);
        }
        __syncthreads();

#pragma unroll 8
        for (int j = 0; j < BKV; j++) {
            float pv[4];
#pragma unroll
            for (int i = 0; i < 4; i++) pv[i] = p_s[r0 + i][j];
            const float4 v4 = *reinterpret_cast<const float4*>(&v_s[j][c0]);
            const float vf[4] = {v4.x, v4.y, v4.z, v4.w};
#pragma unroll
            for (int i = 0; i < 4; i++)
#pragma unroll
                for (int c = 0; c < 4; c++)
                    o[i][c] = fmaf(pv[i], vf[c], o[i][c]);
        }
    }

#pragma unroll
    for (int i = 0; i < 4; i++) {
        const float inv = 1.0f / l[i];
        float* op = g_att + head_off + (size_t)(qb * BQ + r0 + i) * Dd + c0;
        *reinterpret_cast<float4*>(op) =
            make_float4(o[i][0] * inv, o[i][1] * inv, o[i][2] * inv, o[i][3] * inv);
    }
}

// ---------------------------------------------------------------------------
// kernel_launch
// Inputs: 0:x 1:mask(ignored) 2:Wq 3:bq 4:Wk 5:bk 6:Wv 7:bv 8:Wo 9:bo
// ---------------------------------------------------------------------------
extern "C" void kernel_launch(void* const* d_in, const int* in_sizes, int n_in,
                              void* d_out, int out_size)
{
    (void)in_sizes; (void)n_in; (void)out_size;
    const float* x  = (const float*)d_in[0];
    const float* Wq = (const float*)d_in[2];
    const float* bq = (const float*)d_in[3];
    const float* Wk = (const float*)d_in[4];
    const float* bk = (const float*)d_in[5];
    const float* Wv = (const float*)d_in[6];
    const float* bv = (const float*)d_in[7];
    const float* Wo = (const float*)d_in[8];
    const float* bo = (const float*)d_in[9];
    float* out = (float*)d_out;

    cudaFuncSetAttribute(attn_kernel,
                         cudaFuncAttributeMaxDynamicSharedMemorySize, (int)ATT_SMEM);

    split_w_kernel<<<2048, 256>>>(Wq, Wk, Wv, Wo);
    split_x_kernel<<<4096, 256>>>(x);

    dim3 qkv_grid(8, 64, 3);
    gemm_qkv_mma<<<qkv_grid, 256>>>(bq, bk, bv);

    dim3 attn_grid(Ss / BQ, Hh, Bb);
    attn_kernel<<<attn_grid, 256, ATT_SMEM>>>();

    split_att_kernel<<<4096, 256>>>();

    dim3 o_grid(8, 64, 1);
    gemm_o_mma<<<o_grid, 256>>>(bo, out);
}

// round 7
// speedup vs baseline: 2.1862x; 1.5875x over previous
#include <cuda_runtime.h>
#include <cuda_bf16.h>
#include <cstdint>

// Problem constants
constexpr int Bb  = 4;
constexpr int Ss  = 2048;
constexpr int Dd  = 1024;
constexpr int Hh  = 16;
constexpr int DKk = 64;
constexpr int Mm  = Bb * Ss;   // 8192
constexpr int KP  = 3072;      // 3 bf16 segments of 1024

// ---------------------------------------------------------------------------
// Scratch (device globals — no runtime allocation allowed)
// ---------------------------------------------------------------------------
__device__ float g_q[(size_t)Mm * Dd];
__device__ float g_k[(size_t)Mm * Dd];
__device__ float g_v[(size_t)Mm * Dd];
__device__ float g_att[(size_t)Mm * Dd];

// bf16x3 GEMM operand images, row-major, K' = 3072
__device__ __nv_bfloat16 g_xa  [(size_t)Mm * KP];
__device__ __nv_bfloat16 g_atta[(size_t)Mm * KP];
__device__ __nv_bfloat16 g_wa  [(size_t)4 * 1024 * KP];

// Head-blocked bf16 hi|lo images for attention: [(b*16+h)*2048 + s][128]
// cols 0..63 = hi, 64..127 = lo.  Q is pre-scaled by 0.125.
__device__ __nv_bfloat16 g_qs[(size_t)Mm * 128 * Hh / Hh * Hh];  // = Mm*128? no:
// (B*H*S) rows x 128 cols  =  4*16*2048 * 128
__device__ __nv_bfloat16 g_qsx[(size_t)Bb * Hh * Ss * 128];
__device__ __nv_bfloat16 g_ksx[(size_t)Bb * Hh * Ss * 128];
__device__ __nv_bfloat16 g_vsx[(size_t)Bb * Hh * Ss * 128];

// ---------------------------------------------------------------------------
// Helpers
// ---------------------------------------------------------------------------
__device__ __forceinline__ uint32_t smem_u32(const void* p) {
    uint32_t a;
    asm("{ .reg .u64 t; cvta.to.shared.u64 t, %1; cvt.u32.u64 %0, t; }"
        : "=r"(a) : "l"(p));
    return a;
}

__device__ __forceinline__ void ldsm4(uint32_t* r, uint32_t addr) {
    asm volatile("ldmatrix.sync.aligned.m8n8.x4.shared.b16 {%0,%1,%2,%3}, [%4];"
        : "=r"(r[0]), "=r"(r[1]), "=r"(r[2]), "=r"(r[3]) : "r"(addr));
}

__device__ __forceinline__ void ldsm4t(uint32_t* r, uint32_t addr) {
    asm volatile("ldmatrix.sync.aligned.m8n8.x4.trans.shared.b16 {%0,%1,%2,%3}, [%4];"
        : "=r"(r[0]), "=r"(r[1]), "=r"(r[2]), "=r"(r[3]) : "r"(addr));
}

__device__ __forceinline__ void mma16816(float* c, const uint32_t* a,
                                         const uint32_t* b) {
    asm volatile(
        "mma.sync.aligned.m16n8k16.row.col.f32.bf16.bf16.f32 "
        "{%0,%1,%2,%3}, {%4,%5,%6,%7}, {%8,%9}, {%0,%1,%2,%3};"
        : "+f"(c[0]), "+f"(c[1]), "+f"(c[2]), "+f"(c[3])
        : "r"(a[0]), "r"(a[1]), "r"(a[2]), "r"(a[3]), "r"(b[0]), "r"(b[1]));
}

__device__ __forceinline__ void split8(const float* a, uint4& hv, uint4& lv) {
    unsigned short hs[8], ls[8];
#pragma unroll
    for (int j = 0; j < 8; j++) {
        __nv_bfloat16 h = __float2bfloat16(a[j]);
        float r = a[j] - __bfloat162float(h);
        __nv_bfloat16 l = __float2bfloat16(r);
        hs[j] = *reinterpret_cast<unsigned short*>(&h);
        ls[j] = *reinterpret_cast<unsigned short*>(&l);
    }
    hv.x = (uint32_t)hs[0] | ((uint32_t)hs[1] << 16);
    hv.y = (uint32_t)hs[2] | ((uint32_t)hs[3] << 16);
    hv.z = (uint32_t)hs[4] | ((uint32_t)hs[5] << 16);
    hv.w = (uint32_t)hs[6] | ((uint32_t)hs[7] << 16);
    lv.x = (uint32_t)ls[0] | ((uint32_t)ls[1] << 16);
    lv.y = (uint32_t)ls[2] | ((uint32_t)ls[3] << 16);
    lv.z = (uint32_t)ls[4] | ((uint32_t)ls[5] << 16);
    lv.w = (uint32_t)ls[6] | ((uint32_t)ls[7] << 16);
}

// ---------------------------------------------------------------------------
// GEMM-side split kernels (unchanged from R6)
// ---------------------------------------------------------------------------
__device__ __forceinline__ void split_a_body(const float* __restrict__ src,
                                             __nv_bfloat16* __restrict__ dst) {
    const int idx = blockIdx.x * 256 + threadIdx.x;
    const int m  = idx >> 7;
    const int kk = (idx & 127) << 3;
    float a[8];
    const float4 f0 = *reinterpret_cast<const float4*>(src + (size_t)m * 1024 + kk);
    const float4 f1 = *reinterpret_cast<const float4*>(src + (size_t)m * 1024 + kk + 4);
    a[0]=f0.x; a[1]=f0.y; a[2]=f0.z; a[3]=f0.w;
    a[4]=f1.x; a[5]=f1.y; a[6]=f1.z; a[7]=f1.w;
    uint4 hv, lv; split8(a, hv, lv);
    __nv_bfloat16* row = dst + (size_t)m * KP;
    *reinterpret_cast<uint4*>(row + kk)        = hv;
    *reinterpret_cast<uint4*>(row + 1024 + kk) = hv;
    *reinterpret_cast<uint4*>(row + 2048 + kk) = lv;
}

__global__ __launch_bounds__(256)
void split_x_kernel(const float* __restrict__ x) { split_a_body(x, g_xa); }

__global__ __launch_bounds__(256)
void split_att_kernel() { split_a_body(g_att, g_atta); }

__global__ __launch_bounds__(256)
void split_w_kernel(const float* __restrict__ Wq, const float* __restrict__ Wk,
                    const float* __restrict__ Wv, const float* __restrict__ Wo)
{
    const int idx = blockIdx.x * 256 + threadIdx.x;
    const int wi  = idx >> 17;
    const int rem = idx & 131071;
    const int n   = rem >> 7;
    const int kk  = (rem & 127) << 3;
    const float* W = (wi == 0) ? Wq : (wi == 1) ? Wk : (wi == 2) ? Wv : Wo;
    float a[8];
    const float4 f0 = *reinterpret_cast<const float4*>(W + (size_t)n * 1024 + kk);
    const float4 f1 = *reinterpret_cast<const float4*>(W + (size_t)n * 1024 + kk + 4);
    a[0]=f0.x; a[1]=f0.y; a[2]=f0.z; a[3]=f0.w;
    a[4]=f1.x; a[5]=f1.y; a[6]=f1.z; a[7]=f1.w;
    uint4 hv, lv; split8(a, hv, lv);
    __nv_bfloat16* row = g_wa + ((size_t)wi * 1024 + n) * KP;
    *reinterpret_cast<uint4*>(row + kk)        = hv;
    *reinterpret_cast<uint4*>(row + 1024 + kk) = lv;
    *reinterpret_cast<uint4*>(row + 2048 + kk) = hv;
}

// ---------------------------------------------------------------------------
// Split Q/K/V into head-blocked bf16 hi|lo images (Q pre-scaled by 0.125)
// grid: (4096, 1, 3) x 256
// ---------------------------------------------------------------------------
__global__ __launch_bounds__(256)
void split_heads_kernel()
{
    const int which = blockIdx.z;
    const float* src = (which == 0) ? g_q : (which == 1) ? g_k : g_v;
    __nv_bfloat16* dst = (which == 0) ? g_qsx : (which == 1) ? g_ksx : g_vsx;
    const float sc = (which == 0) ? 0.125f : 1.0f;

    const int gi = blockIdx.x * 256 + threadIdx.x;   // < 8192*128
    const int m  = gi >> 7;          // row in [0,8192)
    const int f0 = (gi & 127) << 3;  // feature col 0..1016
    const int h  = f0 >> 6;
    const int fin = f0 & 63;
    const int b  = m >> 11;
    const int s  = m & 2047;

    float a[8];
    const float4 v0 = *reinterpret_cast<const float4*>(src + (size_t)m * 1024 + f0);
    const float4 v1 = *reinterpret_cast<const float4*>(src + (size_t)m * 1024 + f0 + 4);
    a[0]=v0.x*sc; a[1]=v0.y*sc; a[2]=v0.z*sc; a[3]=v0.w*sc;
    a[4]=v1.x*sc; a[5]=v1.y*sc; a[6]=v1.z*sc; a[7]=v1.w*sc;
    uint4 hv, lv; split8(a, hv, lv);
    __nv_bfloat16* row = dst + ((size_t)(b * 16 + h) * 2048 + s) * 128;
    *reinterpret_cast<uint4*>(row + fin)      = hv;
    *reinterpret_cast<uint4*>(row + 64 + fin) = lv;
}

// ---------------------------------------------------------------------------
// bf16 HMMA GEMM (unchanged from R6)
// ---------------------------------------------------------------------------
constexpr int SSTR = 40;
constexpr int NIT  = KP / 32;   // 96

__device__ __forceinline__ void gemm_mma_body(
    const __nv_bfloat16* __restrict__ A,
    const __nv_bfloat16* __restrict__ B,
    const float* __restrict__ bias,
    float* __restrict__ out)
{
    __shared__ __nv_bfloat16 As[2][128][SSTR];
    __shared__ __nv_bfloat16 Bs[2][128][SSTR];

    const int tid  = threadIdx.x;
    const int lane = tid & 31;
    const int wid  = tid >> 5;
    const int wm   = (wid >> 2) * 64;
    const int wn   = (wid & 3) * 32;
    const int bm   = blockIdx.y * 128;
    const int bn   = blockIdx.x * 128;

    const int lr  = tid >> 1;
    const int lcg = (tid & 1) * 16;
    const __nv_bfloat16* Ag = A + (size_t)(bm + lr) * KP + lcg;
    const __nv_bfloat16* Bg = B + (size_t)(bn + lr) * KP + lcg;

    float c[4][4][4];
#pragma unroll
    for (int mt = 0; mt < 4; mt++)
#pragma unroll
        for (int nt = 0; nt < 4; nt++)
#pragma unroll
            for (int i = 0; i < 4; i++) c[mt][nt][i] = 0.f;

    uint4 la0 = *reinterpret_cast<const uint4*>(Ag);
    uint4 la1 = *reinterpret_cast<const uint4*>(Ag + 8);
    uint4 lb0 = *reinterpret_cast<const uint4*>(Bg);
    uint4 lb1 = *reinterpret_cast<const uint4*>(Bg + 8);
    *reinterpret_cast<uint4*>(&As[0][lr][lcg])     = la0;
    *reinterpret_cast<uint4*>(&As[0][lr][lcg + 8]) = la1;
    *reinterpret_cast<uint4*>(&Bs[0][lr][lcg])     = lb0;
    *reinterpret_cast<uint4*>(&Bs[0][lr][lcg + 8]) = lb1;
    __syncthreads();

    const int a_r = (lane & 15);
    const int a_c = (lane >> 4) << 3;
    const int mat = lane >> 3;
    const int b_r = ((mat >> 1) << 3) + (lane & 7);
    const int b_c = (mat & 1) << 3;

    int cur = 0;
    for (int it = 0; it < NIT; it++) {
        if (it + 1 < NIT) {
            const int k0 = (it + 1) * 32;
            la0 = *reinterpret_cast<const uint4*>(Ag + k0);
            la1 = *reinterpret_cast<const uint4*>(Ag + k0 + 8);
            lb0 = *reinterpret_cast<const uint4*>(Bg + k0);
            lb1 = *reinterpret_cast<const uint4*>(Bg + k0 + 8);
        }

#pragma unroll
        for (int ks = 0; ks < 32; ks += 16) {
            uint32_t af[4][4];
#pragma unroll
            for (int mt = 0; mt < 4; mt++)
                ldsm4(af[mt], smem_u32(&As[cur][wm + mt * 16 + a_r][ks + a_c]));
            uint32_t bf[4][2];
#pragma unroll
            for (int p = 0; p < 2; p++) {
                uint32_t t[4];
                ldsm4(t, smem_u32(&Bs[cur][wn + p * 16 + b_r][ks + b_c]));
                bf[p * 2 + 0][0] = t[0]; bf[p * 2 + 0][1] = t[1];
                bf[p * 2 + 1][0] = t[2]; bf[p * 2 + 1][1] = t[3];
            }
#pragma unroll
            for (int mt = 0; mt < 4; mt++)
#pragma unroll
                for (int nt = 0; nt < 4; nt++)
                    mma16816(c[mt][nt], af[mt], bf[nt]);
        }

        if (it + 1 < NIT) {
            const int nb = cur ^ 1;
            *reinterpret_cast<uint4*>(&As[nb][lr][lcg])     = la0;
            *reinterpret_cast<uint4*>(&As[nb][lr][lcg + 8]) = la1;
            *reinterpret_cast<uint4*>(&Bs[nb][lr][lcg])     = lb0;
            *reinterpret_cast<uint4*>(&Bs[nb][lr][lcg + 8]) = lb1;
            __syncthreads();
            cur = nb;
        }
    }

#pragma unroll
    for (int nt = 0; nt < 4; nt++) {
        const int n0 = bn + wn + nt * 8 + (lane & 3) * 2;
        const float b0 = bias[n0], b1 = bias[n0 + 1];
#pragma unroll
        for (int mt = 0; mt < 4; mt++) {
            const int m0 = bm + wm + mt * 16 + (lane >> 2);
            float2 v0 = make_float2(c[mt][nt][0] + b0, c[mt][nt][1] + b1);
            float2 v1 = make_float2(c[mt][nt][2] + b0, c[mt][nt][3] + b1);
            *reinterpret_cast<float2*>(out + (size_t)m0 * 1024 + n0)       = v0;
            *reinterpret_cast<float2*>(out + (size_t)(m0 + 8) * 1024 + n0) = v1;
        }
    }
}

__global__ __launch_bounds__(256)
void gemm_qkv_mma(const float* __restrict__ bq, const float* __restrict__ bk,
                  const float* __restrict__ bv)
{
    const int w = blockIdx.z;
    const float* bias; float* outp;
    if (w == 0)      { bias = bq; outp = g_q; }
    else if (w == 1) { bias = bk; outp = g_k; }
    else             { bias = bv; outp = g_v; }
    gemm_mma_body(g_xa, g_wa + (size_t)w * 1024 * KP, bias, outp);
}

__global__ __launch_bounds__(256)
void gemm_o_mma(const float* __restrict__ bo, float* __restrict__ outp)
{
    gemm_mma_body(g_atta, g_wa + (size_t)3 * 1024 * KP, bo, outp);
}

// ---------------------------------------------------------------------------
// Tensor-core causal flash attention (bf16x3 compensated).
// CTA: 64 q-rows of one (b,h); 4 warps x 16 rows. BKV=64.
// smem: q_s[64][136], k_s[64][136] (hi cols 0..63, lo 64..127),
//       v_s[128][72]  (rows 0..63 = Vhi, 64..127 = Vlo)
// ---------------------------------------------------------------------------
constexpr int QSTR = 136;  // bf16
constexpr int VSTR = 72;
constexpr int ATT_SM_ELEM = 64 * QSTR * 2 + 128 * VSTR;  // 26624 bf16
constexpr size_t ATT_SMEM2 = (size_t)ATT_SM_ELEM * 2;    // 53248 bytes

__global__ __launch_bounds__(128)
void attn_mma_kernel()
{
    extern __shared__ __nv_bfloat16 smb[];
    __nv_bfloat16* q_s = smb;                    // [64][136]
    __nv_bfloat16* k_s = smb + 64 * QSTR;        // [64][136]
    __nv_bfloat16* v_s = smb + 128 * QSTR;       // [128][72]

    const int tid  = threadIdx.x;
    const int lane = tid & 31;
    const int wid  = tid >> 5;          // 0..3
    const int qb   = (Ss / 64 - 1) - blockIdx.x;
    const int h    = blockIdx.y;
    const int b    = blockIdx.z;
    const int bh   = b * Hh + h;

    const __nv_bfloat16* Qg = g_qsx + ((size_t)bh * Ss) * 128;
    const __nv_bfloat16* Kg = g_ksx + ((size_t)bh * Ss) * 128;
    const __nv_bfloat16* Vg = g_vsx + ((size_t)bh * Ss) * 128;

    // ldmatrix lane addressing
    const int a_r = lane & 15;
    const int a_c = (lane >> 4) << 3;
    const int mat = lane >> 3;
    const int b_r = ((mat >> 1) << 3) + (lane & 7);
    const int b_c = (mat & 1) << 3;
    const int v_r = ((mat & 1) << 3) + (lane & 7);
    const int v_c = (lane >> 4) << 3;

    // ---- load Q tile (64 x 128 bf16) and lift to registers ----
    {
        const __nv_bfloat16* src = Qg + (size_t)(qb * 64) * 128;
#pragma unroll
        for (int i = 0; i < 8; i++) {
            const int u = tid + i * 128;        // 0..1023
            const int r = u >> 4, c8 = (u & 15) * 8;
            *reinterpret_cast<uint4*>(&q_s[r * QSTR + c8]) =
                *reinterpret_cast<const uint4*>(src + (size_t)r * 128 + c8);
        }
    }
    __syncthreads();

    uint32_t qh[4][4], ql[4][4];
#pragma unroll
    for (int k4 = 0; k4 < 4; k4++) {
        ldsm4(qh[k4], smem_u32(&q_s[(wid * 16 + a_r) * QSTR + k4 * 16 + a_c]));
        ldsm4(ql[k4], smem_u32(&q_s[(wid * 16 + a_r) * QSTR + 64 + k4 * 16 + a_c]));
    }

    float o[8][4];
#pragma unroll
    for (int nt = 0; nt < 8; nt++)
#pragma unroll
        for (int i = 0; i < 4; i++) o[nt][i] = 0.f;
    float m0 = -1e30f, m1 = -1e30f, l0 = 0.f, l1 = 0.f;

    for (int kb = 0; kb <= qb; kb++) {
        __syncthreads();    // previous iter done reading k_s/v_s
        // ---- load K (64x128) and V (hi 64x64 | lo 64x64) tiles ----
        {
            const __nv_bfloat16* ks = Kg + (size_t)(kb * 64) * 128;
#pragma unroll
            for (int i = 0; i < 8; i++) {
                const int u = tid + i * 128;
                const int r = u >> 4, c8 = (u & 15) * 8;
                *reinterpret_cast<uint4*>(&k_s[r * QSTR + c8]) =
                    *reinterpret_cast<const uint4*>(ks + (size_t)r * 128 + c8);
            }
            const __nv_bfloat16* vs = Vg + (size_t)(kb * 64) * 128;
#pragma unroll
            for (int i = 0; i < 8; i++) {
                const int u = tid + i * 128;        // 0..1023
                const int r = u >> 3;               // 0..127
                const int c8 = (u & 7) * 8;         // 0..56
                const int gc = (r >> 6) ? (64 + c8) : c8;
                *reinterpret_cast<uint4*>(&v_s[r * VSTR + c8]) =
                    *reinterpret_cast<const uint4*>(vs + (size_t)(r & 63) * 128 + gc);
            }
        }
        __syncthreads();

        // ---- scores S = qhi*khi + qhi*klo + qlo*khi ----
        float s[8][4];
#pragma unroll
        for (int nt = 0; nt < 8; nt++)
#pragma unroll
            for (int i = 0; i < 4; i++) s[nt][i] = 0.f;

#pragma unroll
        for (int seg = 0; seg < 3; seg++) {
            const uint32_t (*aa)[4] = (seg < 2) ? qh : ql;
            const int colb = (seg == 1) ? 64 : 0;
#pragma unroll
            for (int k4 = 0; k4 < 4; k4++) {
#pragma unroll
                for (int np = 0; np < 4; np++) {
                    uint32_t t[4];
                    ldsm4(t, smem_u32(&k_s[(np * 16 + b_r) * QSTR + colb + k4 * 16 + b_c]));
                    mma16816(s[np * 2],     aa[k4], t);
                    mma16816(s[np * 2 + 1], aa[k4], t + 2);
                }
            }
        }

        // ---- causal mask on diagonal tile ----
        if (kb == qb) {
            const int row0 = wid * 16 + (lane >> 2);
            const int colb = (lane & 3) * 2;
#pragma unroll
            for (int nt = 0; nt < 8; nt++) {
                const int c = nt * 8 + colb;
                if (c     > row0)     s[nt][0] = -1e30f;
                if (c + 1 > row0)     s[nt][1] = -1e30f;
                if (c     > row0 + 8) s[nt][2] = -1e30f;
                if (c + 1 > row0 + 8) s[nt][3] = -1e30f;
            }
        }

        // ---- online softmax (rows r0 = lane>>2, r1 = r0+8) ----
        float mx0 = -1e30f, mx1 = -1e30f;
#pragma unroll
        for (int nt = 0; nt < 8; nt++) {
            mx0 = fmaxf(mx0, fmaxf(s[nt][0], s[nt][1]));
            mx1 = fmaxf(mx1, fmaxf(s[nt][2], s[nt][3]));
        }
        mx0 = fmaxf(mx0, __shfl_xor_sync(0xffffffffu, mx0, 1));
        mx0 = fmaxf(mx0, __shfl_xor_sync(0xffffffffu, mx0, 2));
        mx1 = fmaxf(mx1, __shfl_xor_sync(0xffffffffu, mx1, 1));
        mx1 = fmaxf(mx1, __shfl_xor_sync(0xffffffffu, mx1, 2));

        const float mn0 = fmaxf(m0, mx0);
        const float mn1 = fmaxf(m1, mx1);
        const float al0 = __expf(m0 - mn0);
        const float al1 = __expf(m1 - mn1);
        m0 = mn0; m1 = mn1;

        float sum0 = 0.f, sum1 = 0.f;
#pragma unroll
        for (int nt = 0; nt < 8; nt++) {
            s[nt][0] = __expf(s[nt][0] - mn0);
            s[nt][1] = __expf(s[nt][1] - mn0);
            s[nt][2] = __expf(s[nt][2] - mn1);
            s[nt][3] = __expf(s[nt][3] - mn1);
            sum0 += s[nt][0] + s[nt][1];
            sum1 += s[nt][2] + s[nt][3];
        }
        sum0 += __shfl_xor_sync(0xffffffffu, sum0, 1);
        sum0 += __shfl_xor_sync(0xffffffffu, sum0, 2);
        sum1 += __shfl_xor_sync(0xffffffffu, sum1, 1);
        sum1 += __shfl_xor_sync(0xffffffffu, sum1, 2);
        l0 = l0 * al0 + sum0;
        l1 = l1 * al1 + sum1;

#pragma unroll
        for (int nt = 0; nt < 8; nt++) {
            o[nt][0] *= al0; o[nt][1] *= al0;
            o[nt][2] *= al1; o[nt][3] *= al1;
        }

        // ---- repack P into A fragments (hi + lo) ----
        uint32_t ph[4][4], pl[4][4];
#pragma unroll
        for (int k4 = 0; k4 < 4; k4++) {
#pragma unroll
            for (int half = 0; half < 2; half++) {     // which score n-tile
                const int nt = k4 * 2 + half;
#pragma unroll
                for (int rr = 0; rr < 2; rr++) {       // row r0 vs r1
                    const float x = s[nt][rr * 2], y = s[nt][rr * 2 + 1];
                    __nv_bfloat162 hp = __floats2bfloat162_rn(x, y);
                    const float lx = x - __bfloat162float(hp.x);
                    const float ly = y - __bfloat162float(hp.y);
                    __nv_bfloat162 lp = __floats2bfloat162_rn(lx, ly);
                    ph[k4][half * 2 + rr] = *reinterpret_cast<uint32_t*>(&hp);
                    pl[k4][half * 2 + rr] = *reinterpret_cast<uint32_t*>(&lp);
                }
            }
        }

        // ---- O += Phi*Vhi + Phi*Vlo + Plo*Vhi ----
#pragma unroll
        for (int seg = 0; seg < 3; seg++) {
            const uint32_t (*aa)[4] = (seg == 2) ? pl : ph;
            const int rb = (seg == 1) ? 64 : 0;
#pragma unroll
            for (int k4 = 0; k4 < 4; k4++) {
#pragma unroll
                for (int np = 0; np < 4; np++) {
                    uint32_t t[4];
                    ldsm4t(t, smem_u32(&v_s[(rb + k4 * 16 + v_r) * VSTR + np * 16 + v_c]));
                    mma16816(o[np * 2],     aa[k4], t);
                    mma16816(o[np * 2 + 1], aa[k4], t + 2);
                }
            }
        }
    }

    // ---- normalize and store to g_att ----
    const float i0 = 1.0f / l0;
    const float i1 = 1.0f / l1;
    const int row0 = qb * 64 + wid * 16 + (lane >> 2);
    const int colb = h * 64 + (lane & 3) * 2;
#pragma unroll
    for (int nt = 0; nt < 8; nt++) {
        const int c = colb + nt * 8;
        *reinterpret_cast<float2*>(g_att + ((size_t)b * Ss + row0) * 1024 + c) =
            make_float2(o[nt][0] * i0, o[nt][1] * i0);
        *reinterpret_cast<float2*>(g_att + ((size_t)b * Ss + row0 + 8) * 1024 + c) =
            make_float2(o[nt][2] * i1, o[nt][3] * i1);
    }
}

// ---------------------------------------------------------------------------
// kernel_launch
// Inputs: 0:x 1:mask(ignored) 2:Wq 3:bq 4:Wk 5:bk 6:Wv 7:bv 8:Wo 9:bo
// ---------------------------------------------------------------------------
extern "C" void kernel_launch(void* const* d_in, const int* in_sizes, int n_in,
                              void* d_out, int out_size)
{
    (void)in_sizes; (void)n_in; (void)out_size;
    const float* x  = (const float*)d_in[0];
    const float* Wq = (const float*)d_in[2];
    const float* bq = (const float*)d_in[3];
    const float* Wk = (const float*)d_in[4];
    const float* bk = (const float*)d_in[5];
    const float* Wv = (const float*)d_in[6];
    const float* bv = (const float*)d_in[7];
    const float* Wo = (const float*)d_in[8];
    const float* bo = (const float*)d_in[9];
    float* out = (float*)d_out;

    cudaFuncSetAttribute(attn_mma_kernel,
                         cudaFuncAttributeMaxDynamicSharedMemorySize, (int)ATT_SMEM2);

    split_w_kernel<<<2048, 256>>>(Wq, Wk, Wv, Wo);
    split_x_kernel<<<4096, 256>>>(x);

    dim3 qkv_grid(8, 64, 3);
    gemm_qkv_mma<<<qkv_grid, 256>>>(bq, bk, bv);

    dim3 sh_grid(4096, 1, 3);
    split_heads_kernel<<<sh_grid, 256>>>();

    dim3 attn_grid(Ss / 64, Hh, Bb);
    attn_mma_kernel<<<attn_grid, 128, ATT_SMEM2>>>();

    split_att_kernel<<<4096, 256>>>();

    dim3 o_grid(8, 64, 1);
    gemm_o_mma<<<o_grid, 256>>>(bo, out);
}

// round 8
// speedup vs baseline: 2.2826x; 1.0441x over previous
#include <cuda_runtime.h>
#include <cuda_bf16.h>
#include <cstdint>

// Problem constants
constexpr int Bb  = 4;
constexpr int Ss  = 2048;
constexpr int Dd  = 1024;
constexpr int Hh  = 16;
constexpr int Mm  = Bb * Ss;   // 8192
constexpr int KP  = 3072;      // 3 bf16 segments of 1024

// ---------------------------------------------------------------------------
// Scratch (device globals — no runtime allocation allowed)
// ---------------------------------------------------------------------------
// bf16x3 GEMM operand images, row-major, K' = 3072
__device__ __nv_bfloat16 g_xa  [(size_t)Mm * KP];   // A' = [xhi | xhi | xlo]
__device__ __nv_bfloat16 g_atta[(size_t)Mm * KP];   // attention out, same layout
__device__ __nv_bfloat16 g_wa  [(size_t)4 * 1024 * KP];  // W' = [whi | wlo | whi]

// Head-blocked bf16 hi|lo images for attention: row (b*16+h)*2048+s, 128 cols
// cols 0..63 = hi, 64..127 = lo.  Q pre-scaled by 0.125.
__device__ __nv_bfloat16 g_qsx[(size_t)Bb * Hh * Ss * 128];
__device__ __nv_bfloat16 g_ksx[(size_t)Bb * Hh * Ss * 128];
__device__ __nv_bfloat16 g_vsx[(size_t)Bb * Hh * Ss * 128];

// ---------------------------------------------------------------------------
// Helpers
// ---------------------------------------------------------------------------
__device__ __forceinline__ uint32_t smem_u32(const void* p) {
    uint32_t a;
    asm("{ .reg .u64 t; cvta.to.shared.u64 t, %1; cvt.u32.u64 %0, t; }"
        : "=r"(a) : "l"(p));
    return a;
}

__device__ __forceinline__ void ldsm4(uint32_t* r, uint32_t addr) {
    asm volatile("ldmatrix.sync.aligned.m8n8.x4.shared.b16 {%0,%1,%2,%3}, [%4];"
        : "=r"(r[0]), "=r"(r[1]), "=r"(r[2]), "=r"(r[3]) : "r"(addr));
}

__device__ __forceinline__ void ldsm4t(uint32_t* r, uint32_t addr) {
    asm volatile("ldmatrix.sync.aligned.m8n8.x4.trans.shared.b16 {%0,%1,%2,%3}, [%4];"
        : "=r"(r[0]), "=r"(r[1]), "=r"(r[2]), "=r"(r[3]) : "r"(addr));
}

__device__ __forceinline__ void mma16816(float* c, const uint32_t* a,
                                         const uint32_t* b) {
    asm volatile(
        "mma.sync.aligned.m16n8k16.row.col.f32.bf16.bf16.f32 "
        "{%0,%1,%2,%3}, {%4,%5,%6,%7}, {%8,%9}, {%0,%1,%2,%3};"
        : "+f"(c[0]), "+f"(c[1]), "+f"(c[2]), "+f"(c[3])
        : "r"(a[0]), "r"(a[1]), "r"(a[2]), "r"(a[3]), "r"(b[0]), "r"(b[1]));
}

__device__ __forceinline__ void cp16(uint32_t dst, const void* src) {
    asm volatile("cp.async.cg.shared.global [%0], [%1], 16;"
                 :: "r"(dst), "l"(src) : "memory");
}
#define CP_COMMIT() asm volatile("cp.async.commit_group;" ::: "memory")
#define CP_WAIT1()  asm volatile("cp.async.wait_group 1;" ::: "memory")
#define CP_WAIT0()  asm volatile("cp.async.wait_group 0;" ::: "memory")

__device__ __forceinline__ void split8(const float* a, uint4& hv, uint4& lv) {
    unsigned short hs[8], ls[8];
#pragma unroll
    for (int j = 0; j < 8; j++) {
        __nv_bfloat16 h = __float2bfloat16(a[j]);
        float r = a[j] - __bfloat162float(h);
        __nv_bfloat16 l = __float2bfloat16(r);
        hs[j] = *reinterpret_cast<unsigned short*>(&h);
        ls[j] = *reinterpret_cast<unsigned short*>(&l);
    }
    hv.x = (uint32_t)hs[0] | ((uint32_t)hs[1] << 16);
    hv.y = (uint32_t)hs[2] | ((uint32_t)hs[3] << 16);
    hv.z = (uint32_t)hs[4] | ((uint32_t)hs[5] << 16);
    hv.w = (uint32_t)hs[6] | ((uint32_t)hs[7] << 16);
    lv.x = (uint32_t)ls[0] | ((uint32_t)ls[1] << 16);
    lv.y = (uint32_t)ls[2] | ((uint32_t)ls[3] << 16);
    lv.z = (uint32_t)ls[4] | ((uint32_t)ls[5] << 16);
    lv.w = (uint32_t)ls[6] | ((uint32_t)ls[7] << 16);
}

// ---------------------------------------------------------------------------
// Input split kernels: fp32 [rows,1024] -> bf16 [rows,3072]
// ---------------------------------------------------------------------------
__global__ __launch_bounds__(256)
void split_x_kernel(const float* __restrict__ x)
{
    const int idx = blockIdx.x * 256 + threadIdx.x;
    const int m  = idx >> 7;
    const int kk = (idx & 127) << 3;
    float a[8];
    const float4 f0 = *reinterpret_cast<const float4*>(x + (size_t)m * 1024 + kk);
    const float4 f1 = *reinterpret_cast<const float4*>(x + (size_t)m * 1024 + kk + 4);
    a[0]=f0.x; a[1]=f0.y; a[2]=f0.z; a[3]=f0.w;
    a[4]=f1.x; a[5]=f1.y; a[6]=f1.z; a[7]=f1.w;
    uint4 hv, lv; split8(a, hv, lv);
    __nv_bfloat16* row = g_xa + (size_t)m * KP;
    *reinterpret_cast<uint4*>(row + kk)        = hv;
    *reinterpret_cast<uint4*>(row + 1024 + kk) = hv;
    *reinterpret_cast<uint4*>(row + 2048 + kk) = lv;
}

__global__ __launch_bounds__(256)
void split_w_kernel(const float* __restrict__ Wq, const float* __restrict__ Wk,
                    const float* __restrict__ Wv, const float* __restrict__ Wo)
{
    const int idx = blockIdx.x * 256 + threadIdx.x;
    const int wi  = idx >> 17;
    const int rem = idx & 131071;
    const int n   = rem >> 7;
    const int kk  = (rem & 127) << 3;
    const float* W = (wi == 0) ? Wq : (wi == 1) ? Wk : (wi == 2) ? Wv : Wo;
    float a[8];
    const float4 f0 = *reinterpret_cast<const float4*>(W + (size_t)n * 1024 + kk);
    const float4 f1 = *reinterpret_cast<const float4*>(W + (size_t)n * 1024 + kk + 4);
    a[0]=f0.x; a[1]=f0.y; a[2]=f0.z; a[3]=f0.w;
    a[4]=f1.x; a[5]=f1.y; a[6]=f1.z; a[7]=f1.w;
    uint4 hv, lv; split8(a, hv, lv);
    __nv_bfloat16* row = g_wa + ((size_t)wi * 1024 + n) * KP;
    *reinterpret_cast<uint4*>(row + kk)        = hv;
    *reinterpret_cast<uint4*>(row + 1024 + kk) = lv;
    *reinterpret_cast<uint4*>(row + 2048 + kk) = hv;
}

// ---------------------------------------------------------------------------
// bf16 HMMA GEMM: C[8192,1024] = A'[8192,3072] * W'[1024,3072]^T + bias
// CTA: 128x128 tile, BK=32, 256 threads = 8 warps (2x4), warp tile 64x32.
// 3-stage cp.async pipeline; padded smem stride 40 bf16.
// MODE 0: epilogue splits into head-blocked bf16 hi|lo (Q/K/V), scale applied.
// MODE 1: epilogue writes fp32 + bias (final output).
// ---------------------------------------------------------------------------
constexpr int SSTR = 40;
constexpr int NIT  = KP / 32;   // 96
constexpr int GEMM_TILE_ELEM = 128 * SSTR;           // per stage per operand
constexpr size_t GEMM_SMEM = (size_t)3 * 2 * GEMM_TILE_ELEM * 2;  // 61440 B

template<int MODE>
__device__ __forceinline__ void gemm_mma_body(
    const __nv_bfloat16* __restrict__ A,
    const __nv_bfloat16* __restrict__ B,
    const float* __restrict__ bias,
    float* __restrict__ outF,
    __nv_bfloat16* __restrict__ outH,
    float qscale)
{
    extern __shared__ __nv_bfloat16 smg[];
    __nv_bfloat16* As = smg;                           // [3][128][SSTR]
    __nv_bfloat16* Bs = smg + 3 * GEMM_TILE_ELEM;      // [3][128][SSTR]

    const int tid  = threadIdx.x;
    const int lane = tid & 31;
    const int wid  = tid >> 5;
    const int wm   = (wid >> 2) * 64;
    const int wn   = (wid & 3) * 32;
    const int bm   = blockIdx.y * 128;
    const int bn   = blockIdx.x * 128;

    const int lr  = tid >> 1;
    const int lcg = (tid & 1) * 16;
    const __nv_bfloat16* Ag = A + (size_t)(bm + lr) * KP + lcg;
    const __nv_bfloat16* Bg = B + (size_t)(bn + lr) * KP + lcg;
    const uint32_t sA = smem_u32(&As[lr * SSTR + lcg]);
    const uint32_t sB = smem_u32(&Bs[lr * SSTR + lcg]);
    const uint32_t stageB = GEMM_TILE_ELEM * 2;        // bytes per stage

    float c[4][4][4];
#pragma unroll
    for (int mt = 0; mt < 4; mt++)
#pragma unroll
        for (int nt = 0; nt < 4; nt++)
#pragma unroll
            for (int i = 0; i < 4; i++) c[mt][nt][i] = 0.f;

    // prologue: stages 0 and 1
#pragma unroll
    for (int p = 0; p < 2; p++) {
        cp16(sA + p * stageB,      Ag + p * 32);
        cp16(sA + p * stageB + 16, Ag + p * 32 + 8);
        cp16(sB + p * stageB,      Bg + p * 32);
        cp16(sB + p * stageB + 16, Bg + p * 32 + 8);
        CP_COMMIT();
    }

    const int a_r = (lane & 15);
    const int a_c = (lane >> 4) << 3;
    const int mat = lane >> 3;
    const int b_r = ((mat >> 1) << 3) + (lane & 7);
    const int b_c = (mat & 1) << 3;

    int cur = 0;
    for (int it = 0; it < NIT; it++) {
        if (it + 2 < NIT) { CP_WAIT1(); } else { CP_WAIT0(); }
        __syncthreads();
        if (it + 2 < NIT) {
            const int st = (it + 2) % 3;
            const int k0 = (it + 2) * 32;
            cp16(sA + st * stageB,      Ag + k0);
            cp16(sA + st * stageB + 16, Ag + k0 + 8);
            cp16(sB + st * stageB,      Bg + k0);
            cp16(sB + st * stageB + 16, Bg + k0 + 8);
            CP_COMMIT();
        }

        const __nv_bfloat16* Ac = As + cur * GEMM_TILE_ELEM;
        const __nv_bfloat16* Bc = Bs + cur * GEMM_TILE_ELEM;
#pragma unroll
        for (int ks = 0; ks < 32; ks += 16) {
            uint32_t af[4][4];
#pragma unroll
            for (int mt = 0; mt < 4; mt++)
                ldsm4(af[mt], smem_u32(&Ac[(wm + mt * 16 + a_r) * SSTR + ks + a_c]));
            uint32_t bf[4][2];
#pragma unroll
            for (int p = 0; p < 2; p++) {
                uint32_t t[4];
                ldsm4(t, smem_u32(&Bc[(wn + p * 16 + b_r) * SSTR + ks + b_c]));
                bf[p * 2 + 0][0] = t[0]; bf[p * 2 + 0][1] = t[1];
                bf[p * 2 + 1][0] = t[2]; bf[p * 2 + 1][1] = t[3];
            }
#pragma unroll
            for (int mt = 0; mt < 4; mt++)
#pragma unroll
                for (int nt = 0; nt < 4; nt++)
                    mma16816(c[mt][nt], af[mt], bf[nt]);
        }
        cur = (cur + 1) % 3;
        __syncthreads();
    }

    if (MODE == 1) {
        // final output: fp32 + bias
#pragma unroll
        for (int nt = 0; nt < 4; nt++) {
            const int n0 = bn + wn + nt * 8 + (lane & 3) * 2;
            const float b0 = bias[n0], b1 = bias[n0 + 1];
#pragma unroll
            for (int mt = 0; mt < 4; mt++) {
                const int m0 = bm + wm + mt * 16 + (lane >> 2);
                float2 v0 = make_float2(c[mt][nt][0] + b0, c[mt][nt][1] + b1);
                float2 v1 = make_float2(c[mt][nt][2] + b0, c[mt][nt][3] + b1);
                *reinterpret_cast<float2*>(outF + (size_t)m0 * 1024 + n0)       = v0;
                *reinterpret_cast<float2*>(outF + (size_t)(m0 + 8) * 1024 + n0) = v1;
            }
        }
    } else {
        // Q/K/V: head-blocked bf16 hi|lo, scale folded in
#pragma unroll
        for (int nt = 0; nt < 4; nt++) {
            const int n0  = bn + wn + nt * 8 + (lane & 3) * 2;
            const int h   = n0 >> 6;
            const int fin = n0 & 63;
            const float b0 = bias[n0], b1 = bias[n0 + 1];
#pragma unroll
            for (int mt = 0; mt < 4; mt++) {
                const int m0 = bm + wm + mt * 16 + (lane >> 2);
#pragma unroll
                for (int rr = 0; rr < 2; rr++) {
                    const int m  = m0 + rr * 8;
                    const float v0 = (c[mt][nt][rr * 2]     + b0) * qscale;
                    const float v1 = (c[mt][nt][rr * 2 + 1] + b1) * qscale;
                    __nv_bfloat162 hp = __floats2bfloat162_rn(v0, v1);
                    __nv_bfloat162 lp = __floats2bfloat162_rn(
                        v0 - __bfloat162float(hp.x), v1 - __bfloat162float(hp.y));
                    __nv_bfloat16* row = outH +
                        ((size_t)((m >> 11) * 16 + h) * 2048 + (m & 2047)) * 128;
                    *reinterpret_cast<uint32_t*>(row + fin) =
                        *reinterpret_cast<uint32_t*>(&hp);
                    *reinterpret_cast<uint32_t*>(row + 64 + fin) =
                        *reinterpret_cast<uint32_t*>(&lp);
                }
            }
        }
    }
}

__global__ __launch_bounds__(256)
void gemm_qkv_mma(const float* __restrict__ bq, const float* __restrict__ bk,
                  const float* __restrict__ bv)
{
    const int w = blockIdx.z;
    const float* bias; __nv_bfloat16* outH; float sc;
    if (w == 0)      { bias = bq; outH = g_qsx; sc = 0.125f; }
    else if (w == 1) { bias = bk; outH = g_ksx; sc = 1.0f; }
    else             { bias = bv; outH = g_vsx; sc = 1.0f; }
    gemm_mma_body<0>(g_xa, g_wa + (size_t)w * 1024 * KP, bias, nullptr, outH, sc);
}

__global__ __launch_bounds__(256)
void gemm_o_mma(const float* __restrict__ bo, float* __restrict__ outp)
{
    gemm_mma_body<1>(g_atta, g_wa + (size_t)3 * 1024 * KP, bo, outp, nullptr, 1.0f);
}

// ---------------------------------------------------------------------------
// Tensor-core causal flash attention (bf16x3 compensated).
// CTA: 64 q-rows of one (b,h); 4 warps x 16 rows. BKV=64.
// Epilogue writes g_atta (bf16x3, K'=3072) directly.
// ---------------------------------------------------------------------------
constexpr int QSTR = 136;
constexpr int VSTR = 72;
constexpr int ATT_SM_ELEM = 64 * QSTR * 2 + 128 * VSTR;
constexpr size_t ATT_SMEM2 = (size_t)ATT_SM_ELEM * 2;   // 53248 bytes

__global__ __launch_bounds__(128)
void attn_mma_kernel()
{
    extern __shared__ __nv_bfloat16 smb[];
    __nv_bfloat16* q_s = smb;                    // [64][136]
    __nv_bfloat16* k_s = smb + 64 * QSTR;        // [64][136]
    __nv_bfloat16* v_s = smb + 128 * QSTR;       // [128][72]

    const int tid  = threadIdx.x;
    const int lane = tid & 31;
    const int wid  = tid >> 5;
    const int qb   = (Ss / 64 - 1) - blockIdx.x;
    const int h    = blockIdx.y;
    const int b    = blockIdx.z;
    const int bh   = b * Hh + h;

    const __nv_bfloat16* Qg = g_qsx + ((size_t)bh * Ss) * 128;
    const __nv_bfloat16* Kg = g_ksx + ((size_t)bh * Ss) * 128;
    const __nv_bfloat16* Vg = g_vsx + ((size_t)bh * Ss) * 128;

    const int a_r = lane & 15;
    const int a_c = (lane >> 4) << 3;
    const int mat = lane >> 3;
    const int b_r = ((mat >> 1) << 3) + (lane & 7);
    const int b_c = (mat & 1) << 3;
    const int v_r = ((mat & 1) << 3) + (lane & 7);
    const int v_c = (lane >> 4) << 3;

    {
        const __nv_bfloat16* src = Qg + (size_t)(qb * 64) * 128;
#pragma unroll
        for (int i = 0; i < 8; i++) {
            const int u = tid + i * 128;
            const int r = u >> 4, c8 = (u & 15) * 8;
            *reinterpret_cast<uint4*>(&q_s[r * QSTR + c8]) =
                *reinterpret_cast<const uint4*>(src + (size_t)r * 128 + c8);
        }
    }
    __syncthreads();

    uint32_t qh[4][4], ql[4][4];
#pragma unroll
    for (int k4 = 0; k4 < 4; k4++) {
        ldsm4(qh[k4], smem_u32(&q_s[(wid * 16 + a_r) * QSTR + k4 * 16 + a_c]));
        ldsm4(ql[k4], smem_u32(&q_s[(wid * 16 + a_r) * QSTR + 64 + k4 * 16 + a_c]));
    }

    float o[8][4];
#pragma unroll
    for (int nt = 0; nt < 8; nt++)
#pragma unroll
        for (int i = 0; i < 4; i++) o[nt][i] = 0.f;
    float m0 = -1e30f, m1 = -1e30f, l0 = 0.f, l1 = 0.f;

    for (int kb = 0; kb <= qb; kb++) {
        __syncthreads();
        {
            const __nv_bfloat16* ks = Kg + (size_t)(kb * 64) * 128;
#pragma unroll
            for (int i = 0; i < 8; i++) {
                const int u = tid + i * 128;
                const int r = u >> 4, c8 = (u & 15) * 8;
                *reinterpret_cast<uint4*>(&k_s[r * QSTR + c8]) =
                    *reinterpret_cast<const uint4*>(ks + (size_t)r * 128 + c8);
            }
            const __nv_bfloat16* vs = Vg + (size_t)(kb * 64) * 128;
#pragma unroll
            for (int i = 0; i < 8; i++) {
                const int u = tid + i * 128;
                const int r = u >> 3;
                const int c8 = (u & 7) * 8;
                const int gc = (r >> 6) ? (64 + c8) : c8;
                *reinterpret_cast<uint4*>(&v_s[r * VSTR + c8]) =
                    *reinterpret_cast<const uint4*>(vs + (size_t)(r & 63) * 128 + gc);
            }
        }
        __syncthreads();

        float s[8][4];
#pragma unroll
        for (int nt = 0; nt < 8; nt++)
#pragma unroll
            for (int i = 0; i < 4; i++) s[nt][i] = 0.f;

#pragma unroll
        for (int seg = 0; seg < 3; seg++) {
            const uint32_t (*aa)[4] = (seg < 2) ? qh : ql;
            const int colb = (seg == 1) ? 64 : 0;
#pragma unroll
            for (int k4 = 0; k4 < 4; k4++) {
#pragma unroll
                for (int np = 0; np < 4; np++) {
                    uint32_t t[4];
                    ldsm4(t, smem_u32(&k_s[(np * 16 + b_r) * QSTR + colb + k4 * 16 + b_c]));
                    mma16816(s[np * 2],     aa[k4], t);
                    mma16816(s[np * 2 + 1], aa[k4], t + 2);
                }
            }
        }

        if (kb == qb) {
            const int row0 = wid * 16 + (lane >> 2);
            const int colb = (lane & 3) * 2;
#pragma unroll
            for (int nt = 0; nt < 8; nt++) {
                const int c = nt * 8 + colb;
                if (c     > row0)     s[nt][0] = -1e30f;
                if (c + 1 > row0)     s[nt][1] = -1e30f;
                if (c     > row0 + 8) s[nt][2] = -1e30f;
                if (c + 1 > row0 + 8) s[nt][3] = -1e30f;
            }
        }

        float mx0 = -1e30f, mx1 = -1e30f;
#pragma unroll
        for (int nt = 0; nt < 8; nt++) {
            mx0 = fmaxf(mx0, fmaxf(s[nt][0], s[nt][1]));
            mx1 = fmaxf(mx1, fmaxf(s[nt][2], s[nt][3]));
        }
        mx0 = fmaxf(mx0, __shfl_xor_sync(0xffffffffu, mx0, 1));
        mx0 = fmaxf(mx0, __shfl_xor_sync(0xffffffffu, mx0, 2));
        mx1 = fmaxf(mx1, __shfl_xor_sync(0xffffffffu, mx1, 1));
        mx1 = fmaxf(mx1, __shfl_xor_sync(0xffffffffu, mx1, 2));

        const float mn0 = fmaxf(m0, mx0);
        const float mn1 = fmaxf(m1, mx1);
        const float al0 = __expf(m0 - mn0);
        const float al1 = __expf(m1 - mn1);
        m0 = mn0; m1 = mn1;

        float sum0 = 0.f, sum1 = 0.f;
#pragma unroll
        for (int nt = 0; nt < 8; nt++) {
            s[nt][0] = __expf(s[nt][0] - mn0);
            s[nt][1] = __expf(s[nt][1] - mn0);
            s[nt][2] = __expf(s[nt][2] - mn1);
            s[nt][3] = __expf(s[nt][3] - mn1);
            sum0 += s[nt][0] + s[nt][1];
            sum1 += s[nt][2] + s[nt][3];
        }
        sum0 += __shfl_xor_sync(0xffffffffu, sum0, 1);
        sum0 += __shfl_xor_sync(0xffffffffu, sum0, 2);
        sum1 += __shfl_xor_sync(0xffffffffu, sum1, 1);
        sum1 += __shfl_xor_sync(0xffffffffu, sum1, 2);
        l0 = l0 * al0 + sum0;
        l1 = l1 * al1 + sum1;

#pragma unroll
        for (int nt = 0; nt < 8; nt++) {
            o[nt][0] *= al0; o[nt][1] *= al0;
            o[nt][2] *= al1; o[nt][3] *= al1;
        }

        uint32_t ph[4][4], pl[4][4];
#pragma unroll
        for (int k4 = 0; k4 < 4; k4++) {
#pragma unroll
            for (int half = 0; half < 2; half++) {
                const int nt = k4 * 2 + half;
#pragma unroll
                for (int rr = 0; rr < 2; rr++) {
                    const float x = s[nt][rr * 2], y = s[nt][rr * 2 + 1];
                    __nv_bfloat162 hp = __floats2bfloat162_rn(x, y);
                    const float lx = x - __bfloat162float(hp.x);
                    const float ly = y - __bfloat162float(hp.y);
                    __nv_bfloat162 lp = __floats2bfloat162_rn(lx, ly);
                    ph[k4][half * 2 + rr] = *reinterpret_cast<uint32_t*>(&hp);
                    pl[k4][half * 2 + rr] = *reinterpret_cast<uint32_t*>(&lp);
                }
            }
        }

#pragma unroll
        for (int seg = 0; seg < 3; seg++) {
            const uint32_t (*aa)[4] = (seg == 2) ? pl : ph;
            const int rb = (seg == 1) ? 64 : 0;
#pragma unroll
            for (int k4 = 0; k4 < 4; k4++) {
#pragma unroll
                for (int np = 0; np < 4; np++) {
                    uint32_t t[4];
                    ldsm4t(t, smem_u32(&v_s[(rb + k4 * 16 + v_r) * VSTR + np * 16 + v_c]));
                    mma16816(o[np * 2],     aa[k4], t);
                    mma16816(o[np * 2 + 1], aa[k4], t + 2);
                }
            }
        }
    }

    // ---- normalize, split to bf16x3, store to g_atta ----
    const float i0 = 1.0f / l0;
    const float i1 = 1.0f / l1;
    const int row0 = qb * 64 + wid * 16 + (lane >> 2);
    const int colb = h * 64 + (lane & 3) * 2;
    __nv_bfloat16* rp0 = g_atta + ((size_t)b * Ss + row0) * KP;
    __nv_bfloat16* rp1 = g_atta + ((size_t)b * Ss + row0 + 8) * KP;
#pragma unroll
    for (int nt = 0; nt < 8; nt++) {
        const int c = colb + nt * 8;
        {
            const float v0 = o[nt][0] * i0, v1 = o[nt][1] * i0;
            __nv_bfloat162 hp = __floats2bfloat162_rn(v0, v1);
            __nv_bfloat162 lp = __floats2bfloat162_rn(
                v0 - __bfloat162float(hp.x), v1 - __bfloat162float(hp.y));
            *reinterpret_cast<uint32_t*>(rp0 + c)        = *reinterpret_cast<uint32_t*>(&hp);
            *reinterpret_cast<uint32_t*>(rp0 + 1024 + c) = *reinterpret_cast<uint32_t*>(&hp);
            *reinterpret_cast<uint32_t*>(rp0 + 2048 + c) = *reinterpret_cast<uint32_t*>(&lp);
        }
        {
            const float v0 = o[nt][2] * i1, v1 = o[nt][3] * i1;
            __nv_bfloat162 hp = __floats2bfloat162_rn(v0, v1);
            __nv_bfloat162 lp = __floats2bfloat162_rn(
                v0 - __bfloat162float(hp.x), v1 - __bfloat162float(hp.y));
            *reinterpret_cast<uint32_t*>(rp1 + c)        = *reinterpret_cast<uint32_t*>(&hp);
            *reinterpret_cast<uint32_t*>(rp1 + 1024 + c) = *reinterpret_cast<uint32_t*>(&hp);
            *reinterpret_cast<uint32_t*>(rp1 + 2048 + c) = *reinterpret_cast<uint32_t*>(&lp);
        }
    }
}

// ---------------------------------------------------------------------------
// kernel_launch
// Inputs: 0:x 1:mask(ignored) 2:Wq 3:bq 4:Wk 5:bk 6:Wv 7:bv 8:Wo 9:bo
// ---------------------------------------------------------------------------
extern "C" void kernel_launch(void* const* d_in, const int* in_sizes, int n_in,
                              void* d_out, int out_size)
{
    (void)in_sizes; (void)n_in; (void)out_size;
    const float* x  = (const float*)d_in[0];
    const float* Wq = (const float*)d_in[2];
    const float* bq = (const float*)d_in[3];
    const float* Wk = (const float*)d_in[4];
    const float* bk = (const float*)d_in[5];
    const float* Wv = (const float*)d_in[6];
    const float* bv = (const float*)d_in[7];
    const float* Wo = (const float*)d_in[8];
    const float* bo = (const float*)d_in[9];
    float* out = (float*)d_out;

    cudaFuncSetAttribute(attn_mma_kernel,
                         cudaFuncAttributeMaxDynamicSharedMemorySize, (int)ATT_SMEM2);
    cudaFuncSetAttribute(gemm_qkv_mma,
                         cudaFuncAttributeMaxDynamicSharedMemorySize, (int)GEMM_SMEM);
    cudaFuncSetAttribute(gemm_o_mma,
                         cudaFuncAttributeMaxDynamicSharedMemorySize, (int)GEMM_SMEM);

    split_w_kernel<<<2048, 256>>>(Wq, Wk, Wv, Wo);
    split_x_kernel<<<4096, 256>>>(x);

    dim3 qkv_grid(8, 64, 3);
    gemm_qkv_mma<<<qkv_grid, 256, GEMM_SMEM>>>(bq, bk, bv);

    dim3 attn_grid(Ss / 64, Hh, Bb);
    attn_mma_kernel<<<attn_grid, 128, ATT_SMEM2>>>();

    dim3 o_grid(8, 64, 1);
    gemm_o_mma<<<o_grid, 256, GEMM_SMEM>>>(bo, out);
}

// round 9
// speedup vs baseline: 3.1520x; 1.3809x over previous
#include <cuda_runtime.h>
#include <cuda_fp16.h>
#include <cstdint>

// Problem constants
constexpr int Bb  = 4;
constexpr int Ss  = 2048;
constexpr int Hh  = 16;
constexpr int Mm  = Bb * Ss;   // 8192
constexpr int KP  = 2048;      // 2 fp16 segments of 1024

// ---------------------------------------------------------------------------
// Scratch (device globals — no runtime allocation allowed)
// ---------------------------------------------------------------------------
// fp16x2 GEMM operand images, row-major, K' = 2048
__device__ __half g_xa  [(size_t)Mm * KP];          // A' = [xhi | xlo]
__device__ __half g_atta[(size_t)Mm * KP];          // attention out [ahi | alo]
__device__ __half g_wa  [(size_t)4 * 1024 * KP];    // W' = [whi | whi]

// Head-blocked fp16 hi|lo images for attention: row (b*16+h)*2048+s, 128 cols
// cols 0..63 = hi, 64..127 = lo.  Q pre-scaled by 0.125.
__device__ __half g_qsx[(size_t)Bb * Hh * Ss * 128];
__device__ __half g_ksx[(size_t)Bb * Hh * Ss * 128];
__device__ __half g_vsx[(size_t)Bb * Hh * Ss * 128];

// ---------------------------------------------------------------------------
// Helpers
// ---------------------------------------------------------------------------
__device__ __forceinline__ uint32_t smem_u32(const void* p) {
    uint32_t a;
    asm("{ .reg .u64 t; cvta.to.shared.u64 t, %1; cvt.u32.u64 %0, t; }"
        : "=r"(a) : "l"(p));
    return a;
}

__device__ __forceinline__ void ldsm4(uint32_t* r, uint32_t addr) {
    asm volatile("ldmatrix.sync.aligned.m8n8.x4.shared.b16 {%0,%1,%2,%3}, [%4];"
        : "=r"(r[0]), "=r"(r[1]), "=r"(r[2]), "=r"(r[3]) : "r"(addr));
}

__device__ __forceinline__ void ldsm4t(uint32_t* r, uint32_t addr) {
    asm volatile("ldmatrix.sync.aligned.m8n8.x4.trans.shared.b16 {%0,%1,%2,%3}, [%4];"
        : "=r"(r[0]), "=r"(r[1]), "=r"(r[2]), "=r"(r[3]) : "r"(addr));
}

__device__ __forceinline__ void mma16816(float* c, const uint32_t* a,
                                         const uint32_t* b) {
    asm volatile(
        "mma.sync.aligned.m16n8k16.row.col.f32.f16.f16.f32 "
        "{%0,%1,%2,%3}, {%4,%5,%6,%7}, {%8,%9}, {%0,%1,%2,%3};"
        : "+f"(c[0]), "+f"(c[1]), "+f"(c[2]), "+f"(c[3])
        : "r"(a[0]), "r"(a[1]), "r"(a[2]), "r"(a[3]), "r"(b[0]), "r"(b[1]));
}

__device__ __forceinline__ void cp16(uint32_t dst, const void* src) {
    asm volatile("cp.async.cg.shared.global [%0], [%1], 16;"
                 :: "r"(dst), "l"(src) : "memory");
}
#define CP_COMMIT() asm volatile("cp.async.commit_group;" ::: "memory")
#define CP_WAIT1()  asm volatile("cp.async.wait_group 1;" ::: "memory")
#define CP_WAIT0()  asm volatile("cp.async.wait_group 0;" ::: "memory")

// fp32 -> (hi, lo) fp16 split of 8 values
__device__ __forceinline__ void split8h(const float* a, uint4& hv, uint4& lv) {
    unsigned short hs[8], ls[8];
#pragma unroll
    for (int j = 0; j < 8; j++) {
        __half h = __float2half_rn(a[j]);
        float r = a[j] - __half2float(h);
        __half l = __float2half_rn(r);
        hs[j] = *reinterpret_cast<unsigned short*>(&h);
        ls[j] = *reinterpret_cast<unsigned short*>(&l);
    }
    hv.x = (uint32_t)hs[0] | ((uint32_t)hs[1] << 16);
    hv.y = (uint32_t)hs[2] | ((uint32_t)hs[3] << 16);
    hv.z = (uint32_t)hs[4] | ((uint32_t)hs[5] << 16);
    hv.w = (uint32_t)hs[6] | ((uint32_t)hs[7] << 16);
    lv.x = (uint32_t)ls[0] | ((uint32_t)ls[1] << 16);
    lv.y = (uint32_t)ls[2] | ((uint32_t)ls[3] << 16);
    lv.z = (uint32_t)ls[4] | ((uint32_t)ls[5] << 16);
    lv.w = (uint32_t)ls[6] | ((uint32_t)ls[7] << 16);
}

__device__ __forceinline__ uint32_t pack_h2(float x, float y) {
    __half2 h = __floats2half2_rn(x, y);
    return *reinterpret_cast<uint32_t*>(&h);
}

// ---------------------------------------------------------------------------
// Input split kernels: fp32 [rows,1024] -> fp16 [rows,2048]
// ---------------------------------------------------------------------------
__global__ __launch_bounds__(256)
void split_x_kernel(const float* __restrict__ x)
{
    const int idx = blockIdx.x * 256 + threadIdx.x;
    const int m  = idx >> 7;
    const int kk = (idx & 127) << 3;
    float a[8];
    const float4 f0 = *reinterpret_cast<const float4*>(x + (size_t)m * 1024 + kk);
    const float4 f1 = *reinterpret_cast<const float4*>(x + (size_t)m * 1024 + kk + 4);
    a[0]=f0.x; a[1]=f0.y; a[2]=f0.z; a[3]=f0.w;
    a[4]=f1.x; a[5]=f1.y; a[6]=f1.z; a[7]=f1.w;
    uint4 hv, lv; split8h(a, hv, lv);
    __half* row = g_xa + (size_t)m * KP;
    *reinterpret_cast<uint4*>(row + kk)        = hv;
    *reinterpret_cast<uint4*>(row + 1024 + kk) = lv;
}

__global__ __launch_bounds__(256)
void split_w_kernel(const float* __restrict__ Wq, const float* __restrict__ Wk,
                    const float* __restrict__ Wv, const float* __restrict__ Wo)
{
    const int idx = blockIdx.x * 256 + threadIdx.x;
    const int wi  = idx >> 17;
    const int rem = idx & 131071;
    const int n   = rem >> 7;
    const int kk  = (rem & 127) << 3;
    const float* W = (wi == 0) ? Wq : (wi == 1) ? Wk : (wi == 2) ? Wv : Wo;
    float a[8];
    const float4 f0 = *reinterpret_cast<const float4*>(W + (size_t)n * 1024 + kk);
    const float4 f1 = *reinterpret_cast<const float4*>(W + (size_t)n * 1024 + kk + 4);
    a[0]=f0.x; a[1]=f0.y; a[2]=f0.z; a[3]=f0.w;
    a[4]=f1.x; a[5]=f1.y; a[6]=f1.z; a[7]=f1.w;
    uint4 hv, lv; split8h(a, hv, lv);
    (void)lv;
    __half* row = g_wa + ((size_t)wi * 1024 + n) * KP;
    *reinterpret_cast<uint4*>(row + kk)        = hv;   // seg0 = hi
    *reinterpret_cast<uint4*>(row + 1024 + kk) = hv;   // seg1 = hi (A carries lo)
}

// ---------------------------------------------------------------------------
// fp16 HMMA GEMM: C[8192,1024] = A'[8192,2048] * W'[1024,2048]^T + bias
// CTA: 128x128 tile, BK=32, 256 threads = 8 warps (2x4), warp tile 64x32.
// 3-stage cp.async pipeline; padded smem stride 40 halves.
// MODE 0: epilogue splits into head-blocked fp16 hi|lo (Q/K/V), scale applied.
// MODE 1: epilogue writes fp32 + bias (final output).
// ---------------------------------------------------------------------------
constexpr int SSTR = 40;
constexpr int NIT  = KP / 32;   // 64
constexpr int GEMM_TILE_ELEM = 128 * SSTR;
constexpr size_t GEMM_SMEM = (size_t)3 * 2 * GEMM_TILE_ELEM * 2;  // 61440 B

template<int MODE>
__device__ __forceinline__ void gemm_mma_body(
    const __half* __restrict__ A,
    const __half* __restrict__ B,
    const float* __restrict__ bias,
    float* __restrict__ outF,
    __half* __restrict__ outH,
    float qscale)
{
    extern __shared__ __half smg[];
    __half* As = smg;                           // [3][128][SSTR]
    __half* Bs = smg + 3 * GEMM_TILE_ELEM;      // [3][128][SSTR]

    const int tid  = threadIdx.x;
    const int lane = tid & 31;
    const int wid  = tid >> 5;
    const int wm   = (wid >> 2) * 64;
    const int wn   = (wid & 3) * 32;
    const int bm   = blockIdx.y * 128;
    const int bn   = blockIdx.x * 128;

    const int lr  = tid >> 1;
    const int lcg = (tid & 1) * 16;
    const __half* Ag = A + (size_t)(bm + lr) * KP + lcg;
    const __half* Bg = B + (size_t)(bn + lr) * KP + lcg;
    const uint32_t sA = smem_u32(&As[lr * SSTR + lcg]);
    const uint32_t sB = smem_u32(&Bs[lr * SSTR + lcg]);
    const uint32_t stageB = GEMM_TILE_ELEM * 2;

    float c[4][4][4];
#pragma unroll
    for (int mt = 0; mt < 4; mt++)
#pragma unroll
        for (int nt = 0; nt < 4; nt++)
#pragma unroll
            for (int i = 0; i < 4; i++) c[mt][nt][i] = 0.f;

#pragma unroll
    for (int p = 0; p < 2; p++) {
        cp16(sA + p * stageB,      Ag + p * 32);
        cp16(sA + p * stageB + 16, Ag + p * 32 + 8);
        cp16(sB + p * stageB,      Bg + p * 32);
        cp16(sB + p * stageB + 16, Bg + p * 32 + 8);
        CP_COMMIT();
    }

    const int a_r = (lane & 15);
    const int a_c = (lane >> 4) << 3;
    const int mat = lane >> 3;
    const int b_r = ((mat >> 1) << 3) + (lane & 7);
    const int b_c = (mat & 1) << 3;

    int cur = 0;
    for (int it = 0; it < NIT; it++) {
        if (it + 2 < NIT) { CP_WAIT1(); } else { CP_WAIT0(); }
        __syncthreads();
        if (it + 2 < NIT) {
            const int st = (it + 2) % 3;
            const int k0 = (it + 2) * 32;
            cp16(sA + st * stageB,      Ag + k0);
            cp16(sA + st * stageB + 16, Ag + k0 + 8);
            cp16(sB + st * stageB,      Bg + k0);
            cp16(sB + st * stageB + 16, Bg + k0 + 8);
            CP_COMMIT();
        }

        const __half* Ac = As + cur * GEMM_TILE_ELEM;
        const __half* Bc = Bs + cur * GEMM_TILE_ELEM;
#pragma unroll
        for (int ks = 0; ks < 32; ks += 16) {
            uint32_t af[4][4];
#pragma unroll
            for (int mt = 0; mt < 4; mt++)
                ldsm4(af[mt], smem_u32(&Ac[(wm + mt * 16 + a_r) * SSTR + ks + a_c]));
            uint32_t bf[4][2];
#pragma unroll
            for (int p = 0; p < 2; p++) {
                uint32_t t[4];
                ldsm4(t, smem_u32(&Bc[(wn + p * 16 + b_r) * SSTR + ks + b_c]));
                bf[p * 2 + 0][0] = t[0]; bf[p * 2 + 0][1] = t[1];
                bf[p * 2 + 1][0] = t[2]; bf[p * 2 + 1][1] = t[3];
            }
#pragma unroll
            for (int mt = 0; mt < 4; mt++)
#pragma unroll
                for (int nt = 0; nt < 4; nt++)
                    mma16816(c[mt][nt], af[mt], bf[nt]);
        }
        cur = (cur + 1) % 3;
        __syncthreads();
    }

    if (MODE == 1) {
#pragma unroll
        for (int nt = 0; nt < 4; nt++) {
            const int n0 = bn + wn + nt * 8 + (lane & 3) * 2;
            const float b0 = bias[n0], b1 = bias[n0 + 1];
#pragma unroll
            for (int mt = 0; mt < 4; mt++) {
                const int m0 = bm + wm + mt * 16 + (lane >> 2);
                float2 v0 = make_float2(c[mt][nt][0] + b0, c[mt][nt][1] + b1);
                float2 v1 = make_float2(c[mt][nt][2] + b0, c[mt][nt][3] + b1);
                *reinterpret_cast<float2*>(outF + (size_t)m0 * 1024 + n0)       = v0;
                *reinterpret_cast<float2*>(outF + (size_t)(m0 + 8) * 1024 + n0) = v1;
            }
        }
    } else {
#pragma unroll
        for (int nt = 0; nt < 4; nt++) {
            const int n0  = bn + wn + nt * 8 + (lane & 3) * 2;
            const int h   = n0 >> 6;
            const int fin = n0 & 63;
            const float b0 = bias[n0], b1 = bias[n0 + 1];
#pragma unroll
            for (int mt = 0; mt < 4; mt++) {
                const int m0 = bm + wm + mt * 16 + (lane >> 2);
#pragma unroll
                for (int rr = 0; rr < 2; rr++) {
                    const int m  = m0 + rr * 8;
                    const float v0 = (c[mt][nt][rr * 2]     + b0) * qscale;
                    const float v1 = (c[mt][nt][rr * 2 + 1] + b1) * qscale;
                    __half2 hp = __floats2half2_rn(v0, v1);
                    __half2 lp = __floats2half2_rn(
                        v0 - __low2float(hp), v1 - __high2float(hp));
                    __half* row = outH +
                        ((size_t)((m >> 11) * 16 + h) * 2048 + (m & 2047)) * 128;
                    *reinterpret_cast<uint32_t*>(row + fin) =
                        *reinterpret_cast<uint32_t*>(&hp);
                    *reinterpret_cast<uint32_t*>(row + 64 + fin) =
                        *reinterpret_cast<uint32_t*>(&lp);
                }
            }
        }
    }
}

__global__ __launch_bounds__(256)
void gemm_qkv_mma(const float* __restrict__ bq, const float* __restrict__ bk,
                  const float* __restrict__ bv)
{
    const int w = blockIdx.z;
    const float* bias; __half* outH; float sc;
    if (w == 0)      { bias = bq; outH = g_qsx; sc = 0.125f; }
    else if (w == 1) { bias = bk; outH = g_ksx; sc = 1.0f; }
    else             { bias = bv; outH = g_vsx; sc = 1.0f; }
    gemm_mma_body<0>(g_xa, g_wa + (size_t)w * 1024 * KP, bias, nullptr, outH, sc);
}

__global__ __launch_bounds__(256)
void gemm_o_mma(const float* __restrict__ bo, float* __restrict__ outp)
{
    gemm_mma_body<1>(g_atta, g_wa + (size_t)3 * 1024 * KP, bo, outp, nullptr, 1.0f);
}

// ---------------------------------------------------------------------------
// Tensor-core causal flash attention (fp16 compensated).
// Scores: 3-term (qh*kh + qh*kl + ql*kh).  PV: 2-term (ph*vh + ph*vl).
// CTA: 64 q-rows of one (b,h); 4 warps x 16 rows. BKV=64.
// Epilogue writes g_atta (fp16 [hi|lo], K'=2048) directly.
// ---------------------------------------------------------------------------
constexpr int QSTR = 136;
constexpr int VSTR = 72;
constexpr int ATT_SM_ELEM = 64 * QSTR * 2 + 128 * VSTR;
constexpr size_t ATT_SMEM2 = (size_t)ATT_SM_ELEM * 2;   // 53248 bytes

__global__ __launch_bounds__(128)
void attn_mma_kernel()
{
    extern __shared__ __half smb[];
    __half* q_s = smb;                    // [64][136]
    __half* k_s = smb + 64 * QSTR;        // [64][136]
    __half* v_s = smb + 128 * QSTR;       // [128][72]

    const int tid  = threadIdx.x;
    const int lane = tid & 31;
    const int wid  = tid >> 5;
    const int qb   = (Ss / 64 - 1) - blockIdx.x;
    const int h    = blockIdx.y;
    const int b    = blockIdx.z;
    const int bh   = b * Hh + h;

    const __half* Qg = g_qsx + ((size_t)bh * Ss) * 128;
    const __half* Kg = g_ksx + ((size_t)bh * Ss) * 128;
    const __half* Vg = g_vsx + ((size_t)bh * Ss) * 128;

    const int a_r = lane & 15;
    const int a_c = (lane >> 4) << 3;
    const int mat = lane >> 3;
    const int b_r = ((mat >> 1) << 3) + (lane & 7);
    const int b_c = (mat & 1) << 3;
    const int v_r = ((mat & 1) << 3) + (lane & 7);
    const int v_c = (lane >> 4) << 3;

    {
        const __half* src = Qg + (size_t)(qb * 64) * 128;
#pragma unroll
        for (int i = 0; i < 8; i++) {
            const int u = tid + i * 128;
            const int r = u >> 4, c8 = (u & 15) * 8;
            *reinterpret_cast<uint4*>(&q_s[r * QSTR + c8]) =
                *reinterpret_cast<const uint4*>(src + (size_t)r * 128 + c8);
        }
    }
    __syncthreads();

    uint32_t qh[4][4], ql[4][4];
#pragma unroll
    for (int k4 = 0; k4 < 4; k4++) {
        ldsm4(qh[k4], smem_u32(&q_s[(wid * 16 + a_r) * QSTR + k4 * 16 + a_c]));
        ldsm4(ql[k4], smem_u32(&q_s[(wid * 16 + a_r) * QSTR + 64 + k4 * 16 + a_c]));
    }

    float o[8][4];
#pragma unroll
    for (int nt = 0; nt < 8; nt++)
#pragma unroll
        for (int i = 0; i < 4; i++) o[nt][i] = 0.f;
    float m0 = -1e30f, m1 = -1e30f, l0 = 0.f, l1 = 0.f;

    for (int kb = 0; kb <= qb; kb++) {
        __syncthreads();
        {
            const __half* ks = Kg + (size_t)(kb * 64) * 128;
#pragma unroll
            for (int i = 0; i < 8; i++) {
                const int u = tid + i * 128;
                const int r = u >> 4, c8 = (u & 15) * 8;
                *reinterpret_cast<uint4*>(&k_s[r * QSTR + c8]) =
                    *reinterpret_cast<const uint4*>(ks + (size_t)r * 128 + c8);
            }
            const __half* vs = Vg + (size_t)(kb * 64) * 128;
#pragma unroll
            for (int i = 0; i < 8; i++) {
                const int u = tid + i * 128;
                const int r = u >> 3;
                const int c8 = (u & 7) * 8;
                const int gc = (r >> 6) ? (64 + c8) : c8;
                *reinterpret_cast<uint4*>(&v_s[r * VSTR + c8]) =
                    *reinterpret_cast<const uint4*>(vs + (size_t)(r & 63) * 128 + gc);
            }
        }
        __syncthreads();

        // scores: 3-term
        float s[8][4];
#pragma unroll
        for (int nt = 0; nt < 8; nt++)
#pragma unroll
            for (int i = 0; i < 4; i++) s[nt][i] = 0.f;

#pragma unroll
        for (int seg = 0; seg < 3; seg++) {
            const uint32_t (*aa)[4] = (seg < 2) ? qh : ql;
            const int colb = (seg == 1) ? 64 : 0;
#pragma unroll
            for (int k4 = 0; k4 < 4; k4++) {
#pragma unroll
                for (int np = 0; np < 4; np++) {
                    uint32_t t[4];
                    ldsm4(t, smem_u32(&k_s[(np * 16 + b_r) * QSTR + colb + k4 * 16 + b_c]));
                    mma16816(s[np * 2],     aa[k4], t);
                    mma16816(s[np * 2 + 1], aa[k4], t + 2);
                }
            }
        }

        if (kb == qb) {
            const int row0 = wid * 16 + (lane >> 2);
            const int colb = (lane & 3) * 2;
#pragma unroll
            for (int nt = 0; nt < 8; nt++) {
                const int c = nt * 8 + colb;
                if (c     > row0)     s[nt][0] = -1e30f;
                if (c + 1 > row0)     s[nt][1] = -1e30f;
                if (c     > row0 + 8) s[nt][2] = -1e30f;
                if (c + 1 > row0 + 8) s[nt][3] = -1e30f;
            }
        }

        float mx0 = -1e30f, mx1 = -1e30f;
#pragma unroll
        for (int nt = 0; nt < 8; nt++) {
            mx0 = fmaxf(mx0, fmaxf(s[nt][0], s[nt][1]));
            mx1 = fmaxf(mx1, fmaxf(s[nt][2], s[nt][3]));
        }
        mx0 = fmaxf(mx0, __shfl_xor_sync(0xffffffffu, mx0, 1));
        mx0 = fmaxf(mx0, __shfl_xor_sync(0xffffffffu, mx0, 2));
        mx1 = fmaxf(mx1, __shfl_xor_sync(0xffffffffu, mx1, 1));
        mx1 = fmaxf(mx1, __shfl_xor_sync(0xffffffffu, mx1, 2));

        const float mn0 = fmaxf(m0, mx0);
        const float mn1 = fmaxf(m1, mx1);
        const float al0 = __expf(m0 - mn0);
        const float al1 = __expf(m1 - mn1);
        m0 = mn0; m1 = mn1;

        float sum0 = 0.f, sum1 = 0.f;
#pragma unroll
        for (int nt = 0; nt < 8; nt++) {
            s[nt][0] = __expf(s[nt][0] - mn0);
            s[nt][1] = __expf(s[nt][1] - mn0);
            s[nt][2] = __expf(s[nt][2] - mn1);
            s[nt][3] = __expf(s[nt][3] - mn1);
            sum0 += s[nt][0] + s[nt][1];
            sum1 += s[nt][2] + s[nt][3];
        }
        sum0 += __shfl_xor_sync(0xffffffffu, sum0, 1);
        sum0 += __shfl_xor_sync(0xffffffffu, sum0, 2);
        sum1 += __shfl_xor_sync(0xffffffffu, sum1, 1);
        sum1 += __shfl_xor_sync(0xffffffffu, sum1, 2);
        l0 = l0 * al0 + sum0;
        l1 = l1 * al1 + sum1;

#pragma unroll
        for (int nt = 0; nt < 8; nt++) {
            o[nt][0] *= al0; o[nt][1] *= al0;
            o[nt][2] *= al1; o[nt][3] *= al1;
        }

        // repack P (hi only) into A fragments
        uint32_t ph[4][4];
#pragma unroll
        for (int k4 = 0; k4 < 4; k4++) {
#pragma unroll
            for (int half = 0; half < 2; half++) {
                const int nt = k4 * 2 + half;
#pragma unroll
                for (int rr = 0; rr < 2; rr++) {
                    ph[k4][half * 2 + rr] =
                        pack_h2(s[nt][rr * 2], s[nt][rr * 2 + 1]);
                }
            }
        }

        // O += Ph*Vhi + Ph*Vlo
#pragma unroll
        for (int seg = 0; seg < 2; seg++) {
            const int rb = seg * 64;
#pragma unroll
            for (int k4 = 0; k4 < 4; k4++) {
#pragma unroll
                for (int np = 0; np < 4; np++) {
                    uint32_t t[4];
                    ldsm4t(t, smem_u32(&v_s[(rb + k4 * 16 + v_r) * VSTR + np * 16 + v_c]));
                    mma16816(o[np * 2],     ph[k4], t);
                    mma16816(o[np * 2 + 1], ph[k4], t + 2);
                }
            }
        }
    }

    // normalize, split to fp16 hi|lo, store to g_atta (K'=2048)
    const float i0 = 1.0f / l0;
    const float i1 = 1.0f / l1;
    const int row0 = qb * 64 + wid * 16 + (lane >> 2);
    const int colb = h * 64 + (lane & 3) * 2;
    __half* rp0 = g_atta + ((size_t)b * Ss + row0) * KP;
    __half* rp1 = g_atta + ((size_t)b * Ss + row0 + 8) * KP;
#pragma unroll
    for (int nt = 0; nt < 8; nt++) {
        const int c = colb + nt * 8;
        {
            const float v0 = o[nt][0] * i0, v1 = o[nt][1] * i0;
            __half2 hp = __floats2half2_rn(v0, v1);
            __half2 lp = __floats2half2_rn(
                v0 - __low2float(hp), v1 - __high2float(hp));
            *reinterpret_cast<uint32_t*>(rp0 + c)        = *reinterpret_cast<uint32_t*>(&hp);
            *reinterpret_cast<uint32_t*>(rp0 + 1024 + c) = *reinterpret_cast<uint32_t*>(&lp);
        }
        {
            const float v0 = o[nt][2] * i1, v1 = o[nt][3] * i1;
            __half2 hp = __floats2half2_rn(v0, v1);
            __half2 lp = __floats2half2_rn(
                v0 - __low2float(hp), v1 - __high2float(hp));
            *reinterpret_cast<uint32_t*>(rp1 + c)        = *reinterpret_cast<uint32_t*>(&hp);
            *reinterpret_cast<uint32_t*>(rp1 + 1024 + c) = *reinterpret_cast<uint32_t*>(&lp);
        }
    }
}

// ---------------------------------------------------------------------------
// kernel_launch
// Inputs: 0:x 1:mask(ignored) 2:Wq 3:bq 4:Wk 5:bk 6:Wv 7:bv 8:Wo 9:bo
// ---------------------------------------------------------------------------
extern "C" void kernel_launch(void* const* d_in, const int* in_sizes, int n_in,
                              void* d_out, int out_size)
{
    (void)in_sizes; (void)n_in; (void)out_size;
    const float* x  = (const float*)d_in[0];
    const float* Wq = (const float*)d_in[2];
    const float* bq = (const float*)d_in[3];
    const float* Wk = (const float*)d_in[4];
    const float* bk = (const float*)d_in[5];
    const float* Wv = (const float*)d_in[6];
    const float* bv = (const float*)d_in[7];
    const float* Wo = (const float*)d_in[8];
    const float* bo = (const float*)d_in[9];
    float* out = (float*)d_out;

    cudaFuncSetAttribute(attn_mma_kernel,
                         cudaFuncAttributeMaxDynamicSharedMemorySize, (int)ATT_SMEM2);
    cudaFuncSetAttribute(gemm_qkv_mma,
                         cudaFuncAttributeMaxDynamicSharedMemorySize, (int)GEMM_SMEM);
    cudaFuncSetAttribute(gemm_o_mma,
                         cudaFuncAttributeMaxDynamicSharedMemorySize, (int)GEMM_SMEM);

    split_w_kernel<<<2048, 256>>>(Wq, Wk, Wv, Wo);
    split_x_kernel<<<4096, 256>>>(x);

    dim3 qkv_grid(8, 64, 3);
    gemm_qkv_mma<<<qkv_grid, 256, GEMM_SMEM>>>(bq, bk, bv);

    dim3 attn_grid(Ss / 64, Hh, Bb);
    attn_mma_kernel<<<attn_grid, 128, ATT_SMEM2>>>();

    dim3 o_grid(8, 64, 1);
    gemm_o_mma<<<o_grid, 256, GEMM_SMEM>>>(bo, out);
}

// round 10
// speedup vs baseline: 3.1758x; 1.0076x over previous
#include <cuda_runtime.h>
#include <cuda_fp16.h>
#include <cstdint>

// Problem constants
constexpr int Bb  = 4;
constexpr int Ss  = 2048;
constexpr int Hh  = 16;
constexpr int Mm  = Bb * Ss;   // 8192
constexpr int KP  = 2048;      // 2 fp16 segments of 1024

// ---------------------------------------------------------------------------
// Scratch (device globals — no runtime allocation allowed)
// ---------------------------------------------------------------------------
__device__ __half g_xa  [(size_t)Mm * KP];          // A' = [xhi | xlo]
__device__ __half g_atta[(size_t)Mm * KP];          // attention out [ahi | alo]
__device__ __half g_wa  [(size_t)4 * 1024 * KP];    // W' = [whi | whi]

// Head-blocked fp16 hi|lo images: row (b*16+h)*2048+s, 128 cols
// cols 0..63 = hi, 64..127 = lo.  Q pre-scaled by 0.125.
__device__ __half g_qsx[(size_t)Bb * Hh * Ss * 128];
__device__ __half g_ksx[(size_t)Bb * Hh * Ss * 128];
__device__ __half g_vsx[(size_t)Bb * Hh * Ss * 128];

// ---------------------------------------------------------------------------
// Helpers
// ---------------------------------------------------------------------------
__device__ __forceinline__ uint32_t smem_u32(const void* p) {
    uint32_t a;
    asm("{ .reg .u64 t; cvta.to.shared.u64 t, %1; cvt.u32.u64 %0, t; }"
        : "=r"(a) : "l"(p));
    return a;
}

__device__ __forceinline__ void ldsm4(uint32_t* r, uint32_t addr) {
    asm volatile("ldmatrix.sync.aligned.m8n8.x4.shared.b16 {%0,%1,%2,%3}, [%4];"
        : "=r"(r[0]), "=r"(r[1]), "=r"(r[2]), "=r"(r[3]) : "r"(addr));
}

__device__ __forceinline__ void ldsm4t(uint32_t* r, uint32_t addr) {
    asm volatile("ldmatrix.sync.aligned.m8n8.x4.trans.shared.b16 {%0,%1,%2,%3}, [%4];"
        : "=r"(r[0]), "=r"(r[1]), "=r"(r[2]), "=r"(r[3]) : "r"(addr));
}

__device__ __forceinline__ void mma16816(float* c, const uint32_t* a,
                                         const uint32_t* b) {
    asm volatile(
        "mma.sync.aligned.m16n8k16.row.col.f32.f16.f16.f32 "
        "{%0,%1,%2,%3}, {%4,%5,%6,%7}, {%8,%9}, {%0,%1,%2,%3};"
        : "+f"(c[0]), "+f"(c[1]), "+f"(c[2]), "+f"(c[3])
        : "r"(a[0]), "r"(a[1]), "r"(a[2]), "r"(a[3]), "r"(b[0]), "r"(b[1]));
}

__device__ __forceinline__ void cp16(uint32_t dst, const void* src) {
    asm volatile("cp.async.cg.shared.global [%0], [%1], 16;"
                 :: "r"(dst), "l"(src) : "memory");
}
#define CP_COMMIT() asm volatile("cp.async.commit_group;" ::: "memory")
#define CP_WAIT1()  asm volatile("cp.async.wait_group 1;" ::: "memory")
#define CP_WAIT0()  asm volatile("cp.async.wait_group 0;" ::: "memory")

// fp32 -> (hi, lo) fp16 split of 8 values
__device__ __forceinline__ void split8h(const float* a, uint4& hv, uint4& lv) {
    unsigned short hs[8], ls[8];
#pragma unroll
    for (int j = 0; j < 8; j++) {
        __half h = __float2half_rn(a[j]);
        float r = a[j] - __half2float(h);
        __half l = __float2half_rn(r);
        hs[j] = *reinterpret_cast<unsigned short*>(&h);
        ls[j] = *reinterpret_cast<unsigned short*>(&l);
    }
    hv.x = (uint32_t)hs[0] | ((uint32_t)hs[1] << 16);
    hv.y = (uint32_t)hs[2] | ((uint32_t)hs[3] << 16);
    hv.z = (uint32_t)hs[4] | ((uint32_t)hs[5] << 16);
    hv.w = (uint32_t)hs[6] | ((uint32_t)hs[7] << 16);
    lv.x = (uint32_t)ls[0] | ((uint32_t)ls[1] << 16);
    lv.y = (uint32_t)ls[2] | ((uint32_t)ls[3] << 16);
    lv.z = (uint32_t)ls[4] | ((uint32_t)ls[5] << 16);
    lv.w = (uint32_t)ls[6] | ((uint32_t)ls[7] << 16);
}

__device__ __forceinline__ uint32_t pack_h2(float x, float y) {
    __half2 h = __floats2half2_rn(x, y);
    return *reinterpret_cast<uint32_t*>(&h);
}

// ---------------------------------------------------------------------------
// Input split kernels: fp32 [rows,1024] -> fp16 [rows,2048]
// ---------------------------------------------------------------------------
__global__ __launch_bounds__(256)
void split_x_kernel(const float* __restrict__ x)
{
    const int idx = blockIdx.x * 256 + threadIdx.x;
    const int m  = idx >> 7;
    const int kk = (idx & 127) << 3;
    float a[8];
    const float4 f0 = *reinterpret_cast<const float4*>(x + (size_t)m * 1024 + kk);
    const float4 f1 = *reinterpret_cast<const float4*>(x + (size_t)m * 1024 + kk + 4);
    a[0]=f0.x; a[1]=f0.y; a[2]=f0.z; a[3]=f0.w;
    a[4]=f1.x; a[5]=f1.y; a[6]=f1.z; a[7]=f1.w;
    uint4 hv, lv; split8h(a, hv, lv);
    __half* row = g_xa + (size_t)m * KP;
    *reinterpret_cast<uint4*>(row + kk)        = hv;
    *reinterpret_cast<uint4*>(row + 1024 + kk) = lv;
}

__global__ __launch_bounds__(256)
void split_w_kernel(const float* __restrict__ Wq, const float* __restrict__ Wk,
                    const float* __restrict__ Wv, const float* __restrict__ Wo)
{
    const int idx = blockIdx.x * 256 + threadIdx.x;
    const int wi  = idx >> 17;
    const int rem = idx & 131071;
    const int n   = rem >> 7;
    const int kk  = (rem & 127) << 3;
    const float* W = (wi == 0) ? Wq : (wi == 1) ? Wk : (wi == 2) ? Wv : Wo;
    float a[8];
    const float4 f0 = *reinterpret_cast<const float4*>(W + (size_t)n * 1024 + kk);
    const float4 f1 = *reinterpret_cast<const float4*>(W + (size_t)n * 1024 + kk + 4);
    a[0]=f0.x; a[1]=f0.y; a[2]=f0.z; a[3]=f0.w;
    a[4]=f1.x; a[5]=f1.y; a[6]=f1.z; a[7]=f1.w;
    uint4 hv, lv; split8h(a, hv, lv);
    (void)lv;
    __half* row = g_wa + ((size_t)wi * 1024 + n) * KP;
    *reinterpret_cast<uint4*>(row + kk)        = hv;
    *reinterpret_cast<uint4*>(row + 1024 + kk) = hv;
}

// ---------------------------------------------------------------------------
// fp16 HMMA GEMM: C[8192,1024] = A'[8192,2048] * W'[1024,2048]^T + bias
// CTA: 128x128 tile, BK=32, 256 threads = 8 warps (2x4), warp tile 64x32.
// 3-stage cp.async pipeline; ONE __syncthreads per K-chunk.
// ---------------------------------------------------------------------------
constexpr int SSTR = 40;
constexpr int NIT  = KP / 32;   // 64
constexpr int GEMM_TILE_ELEM = 128 * SSTR;
constexpr size_t GEMM_SMEM = (size_t)3 * 2 * GEMM_TILE_ELEM * 2;  // 61440 B

template<int MODE>
__device__ __forceinline__ void gemm_mma_body(
    const __half* __restrict__ A,
    const __half* __restrict__ B,
    const float* __restrict__ bias,
    float* __restrict__ outF,
    __half* __restrict__ outH,
    float qscale)
{
    extern __shared__ __half smg[];
    __half* As = smg;
    __half* Bs = smg + 3 * GEMM_TILE_ELEM;

    const int tid  = threadIdx.x;
    const int lane = tid & 31;
    const int wid  = tid >> 5;
    const int wm   = (wid >> 2) * 64;
    const int wn   = (wid & 3) * 32;
    const int bm   = blockIdx.y * 128;
    const int bn   = blockIdx.x * 128;

    const int lr  = tid >> 1;
    const int lcg = (tid & 1) * 16;
    const __half* Ag = A + (size_t)(bm + lr) * KP + lcg;
    const __half* Bg = B + (size_t)(bn + lr) * KP + lcg;
    const uint32_t sA = smem_u32(&As[lr * SSTR + lcg]);
    const uint32_t sB = smem_u32(&Bs[lr * SSTR + lcg]);
    const uint32_t stageB = GEMM_TILE_ELEM * 2;

    float c[4][4][4];
#pragma unroll
    for (int mt = 0; mt < 4; mt++)
#pragma unroll
        for (int nt = 0; nt < 4; nt++)
#pragma unroll
            for (int i = 0; i < 4; i++) c[mt][nt][i] = 0.f;

#pragma unroll
    for (int p = 0; p < 2; p++) {
        cp16(sA + p * stageB,      Ag + p * 32);
        cp16(sA + p * stageB + 16, Ag + p * 32 + 8);
        cp16(sB + p * stageB,      Bg + p * 32);
        cp16(sB + p * stageB + 16, Bg + p * 32 + 8);
        CP_COMMIT();
    }

    const int a_r = (lane & 15);
    const int a_c = (lane >> 4) << 3;
    const int mat = lane >> 3;
    const int b_r = ((mat >> 1) << 3) + (lane & 7);
    const int b_c = (mat & 1) << 3;

    int cur = 0;
    for (int it = 0; it < NIT; it++) {
        if (it + 2 < NIT) { CP_WAIT1(); } else { CP_WAIT0(); }
        __syncthreads();
        if (it + 2 < NIT) {
            const int st = (it + 2) % 3;
            const int k0 = (it + 2) * 32;
            cp16(sA + st * stageB,      Ag + k0);
            cp16(sA + st * stageB + 16, Ag + k0 + 8);
            cp16(sB + st * stageB,      Bg + k0);
            cp16(sB + st * stageB + 16, Bg + k0 + 8);
            CP_COMMIT();
        }

        const __half* Ac = As + cur * GEMM_TILE_ELEM;
        const __half* Bc = Bs + cur * GEMM_TILE_ELEM;
#pragma unroll
        for (int ks = 0; ks < 32; ks += 16) {
            uint32_t af[4][4];
#pragma unroll
            for (int mt = 0; mt < 4; mt++)
                ldsm4(af[mt], smem_u32(&Ac[(wm + mt * 16 + a_r) * SSTR + ks + a_c]));
            uint32_t bf[4][2];
#pragma unroll
            for (int p = 0; p < 2; p++) {
                uint32_t t[4];
                ldsm4(t, smem_u32(&Bc[(wn + p * 16 + b_r) * SSTR + ks + b_c]));
                bf[p * 2 + 0][0] = t[0]; bf[p * 2 + 0][1] = t[1];
                bf[p * 2 + 1][0] = t[2]; bf[p * 2 + 1][1] = t[3];
            }
#pragma unroll
            for (int mt = 0; mt < 4; mt++)
#pragma unroll
                for (int nt = 0; nt < 4; nt++)
                    mma16816(c[mt][nt], af[mt], bf[nt]);
        }
        cur = (cur + 1) % 3;
        // NOTE: no trailing barrier — the top-of-iter barrier orders the
        // next prefetch against this iteration's readers.
    }
    __syncthreads();

    if (MODE == 1) {
#pragma unroll
        for (int nt = 0; nt < 4; nt++) {
            const int n0 = bn + wn + nt * 8 + (lane & 3) * 2;
            const float b0 = bias[n0], b1 = bias[n0 + 1];
#pragma unroll
            for (int mt = 0; mt < 4; mt++) {
                const int m0 = bm + wm + mt * 16 + (lane >> 2);
                float2 v0 = make_float2(c[mt][nt][0] + b0, c[mt][nt][1] + b1);
                float2 v1 = make_float2(c[mt][nt][2] + b0, c[mt][nt][3] + b1);
                *reinterpret_cast<float2*>(outF + (size_t)m0 * 1024 + n0)       = v0;
                *reinterpret_cast<float2*>(outF + (size_t)(m0 + 8) * 1024 + n0) = v1;
            }
        }
    } else {
#pragma unroll
        for (int nt = 0; nt < 4; nt++) {
            const int n0  = bn + wn + nt * 8 + (lane & 3) * 2;
            const int h   = n0 >> 6;
            const int fin = n0 & 63;
            const float b0 = bias[n0], b1 = bias[n0 + 1];
#pragma unroll
            for (int mt = 0; mt < 4; mt++) {
                const int m0 = bm + wm + mt * 16 + (lane >> 2);
#pragma unroll
                for (int rr = 0; rr < 2; rr++) {
                    const int m  = m0 + rr * 8;
                    const float v0 = (c[mt][nt][rr * 2]     + b0) * qscale;
                    const float v1 = (c[mt][nt][rr * 2 + 1] + b1) * qscale;
                    __half2 hp = __floats2half2_rn(v0, v1);
                    __half2 lp = __floats2half2_rn(
                        v0 - __low2float(hp), v1 - __high2float(hp));
                    __half* row = outH +
                        ((size_t)((m >> 11) * 16 + h) * 2048 + (m & 2047)) * 128;
                    *reinterpret_cast<uint32_t*>(row + fin) =
                        *reinterpret_cast<uint32_t*>(&hp);
                    *reinterpret_cast<uint32_t*>(row + 64 + fin) =
                        *reinterpret_cast<uint32_t*>(&lp);
                }
            }
        }
    }
}

__global__ __launch_bounds__(256)
void gemm_qkv_mma(const float* __restrict__ bq, const float* __restrict__ bk,
                  const float* __restrict__ bv)
{
    const int w = blockIdx.z;
    const float* bias; __half* outH; float sc;
    if (w == 0)      { bias = bq; outH = g_qsx; sc = 0.125f; }
    else if (w == 1) { bias = bk; outH = g_ksx; sc = 1.0f; }
    else             { bias = bv; outH = g_vsx; sc = 1.0f; }
    gemm_mma_body<0>(g_xa, g_wa + (size_t)w * 1024 * KP, bias, nullptr, outH, sc);
}

__global__ __launch_bounds__(256)
void gemm_o_mma(const float* __restrict__ bo, float* __restrict__ outp)
{
    gemm_mma_body<1>(g_atta, g_wa + (size_t)3 * 1024 * KP, bo, outp, nullptr, 1.0f);
}

// ---------------------------------------------------------------------------
// Tensor-core causal flash attention (fp16 compensated).
// Scores: 3-term (qh*kh + qh*kl + ql*kh).  PV: 2-term (ph*vh + ph*vl).
// CTA: 64 q-rows of one (b,h); 4 warps x 16 rows. BKV=64.
// Double-buffered cp.async K/V prefetch; ONE __syncthreads per kv-tile.
// ---------------------------------------------------------------------------
constexpr int QSTR = 136;
constexpr int VSTR = 72;
constexpr int QELEM = 64 * QSTR;     // 8704 halves per K/Q tile buffer
constexpr int VELEM = 128 * VSTR;    // 9216 halves per V tile buffer
constexpr size_t ATT_SMEM2 = (size_t)(QELEM + 2 * QELEM + 2 * VELEM) * 2; // 89088 B

__global__ __launch_bounds__(128)
void attn_mma_kernel()
{
    extern __shared__ __half smb[];
    __half* q_s  = smb;                       // [64][136]
    __half* k_sb = smb + QELEM;               // 2 x [64][136]
    __half* v_sb = smb + 3 * QELEM;           // 2 x [128][72]

    const int tid  = threadIdx.x;
    const int lane = tid & 31;
    const int wid  = tid >> 5;
    const int qb   = (Ss / 64 - 1) - blockIdx.x;
    const int h    = blockIdx.y;
    const int b    = blockIdx.z;
    const int bh   = b * Hh + h;

    const __half* Qg = g_qsx + ((size_t)bh * Ss) * 128;
    const __half* Kg = g_ksx + ((size_t)bh * Ss) * 128;
    const __half* Vg = g_vsx + ((size_t)bh * Ss) * 128;

    // per-thread load coordinates (same mapping as before, via cp.async)
    const int k_r  = (tid >> 4) * 8;          // base rows handled over i
    const int v_base = tid;                   // kept simple below

    const int a_r = lane & 15;
    const int a_c = (lane >> 4) << 3;
    const int mat = lane >> 3;
    const int b_r = ((mat >> 1) << 3) + (lane & 7);
    const int b_c = (mat & 1) << 3;
    const int v_r = ((mat & 1) << 3) + (lane & 7);
    const int v_c = (lane >> 4) << 3;
    (void)k_r; (void)v_base;

    // ---- prologue: prefetch K/V tile 0, load Q synchronously ----
    {
        const __half* ks = Kg;   // kb = 0
        const __half* vs = Vg;
#pragma unroll
        for (int i = 0; i < 8; i++) {
            const int u = tid + i * 128;
            const int r = u >> 4, c8 = (u & 15) * 8;
            cp16(smem_u32(&k_sb[r * QSTR + c8]), ks + (size_t)r * 128 + c8);
        }
#pragma unroll
        for (int i = 0; i < 8; i++) {
            const int u = tid + i * 128;
            const int r = u >> 3;
            const int c8 = (u & 7) * 8;
            const int gc = (r >> 6) ? (64 + c8) : c8;
            cp16(smem_u32(&v_sb[r * VSTR + c8]), vs + (size_t)(r & 63) * 128 + gc);
        }
        CP_COMMIT();

        const __half* src = Qg + (size_t)(qb * 64) * 128;
#pragma unroll
        for (int i = 0; i < 8; i++) {
            const int u = tid + i * 128;
            const int r = u >> 4, c8 = (u & 15) * 8;
            *reinterpret_cast<uint4*>(&q_s[r * QSTR + c8]) =
                *reinterpret_cast<const uint4*>(src + (size_t)r * 128 + c8);
        }
    }
    CP_WAIT0();
    __syncthreads();

    uint32_t qh[4][4], ql[4][4];
#pragma unroll
    for (int k4 = 0; k4 < 4; k4++) {
        ldsm4(qh[k4], smem_u32(&q_s[(wid * 16 + a_r) * QSTR + k4 * 16 + a_c]));
        ldsm4(ql[k4], smem_u32(&q_s[(wid * 16 + a_r) * QSTR + 64 + k4 * 16 + a_c]));
    }

    float o[8][4];
#pragma unroll
    for (int nt = 0; nt < 8; nt++)
#pragma unroll
        for (int i = 0; i < 4; i++) o[nt][i] = 0.f;
    float m0 = -1e30f, m1 = -1e30f, l0 = 0.f, l1 = 0.f;

    for (int kb = 0; kb <= qb; kb++) {
        const int buf = kb & 1;
        __half* kc = k_sb + buf * QELEM;
        __half* vc = v_sb + buf * VELEM;

        // prefetch next tile into the other buffer (safe: end-of-prev-iter
        // barrier ordered all readers of that buffer)
        if (kb < qb) {
            const int nbuf = buf ^ 1;
            const __half* ks = Kg + (size_t)((kb + 1) * 64) * 128;
            const __half* vs = Vg + (size_t)((kb + 1) * 64) * 128;
            __half* kd = k_sb + nbuf * QELEM;
            __half* vd = v_sb + nbuf * VELEM;
#pragma unroll
            for (int i = 0; i < 8; i++) {
                const int u = tid + i * 128;
                const int r = u >> 4, c8 = (u & 15) * 8;
                cp16(smem_u32(&kd[r * QSTR + c8]), ks + (size_t)r * 128 + c8);
            }
#pragma unroll
            for (int i = 0; i < 8; i++) {
                const int u = tid + i * 128;
                const int r = u >> 3;
                const int c8 = (u & 7) * 8;
                const int gc = (r >> 6) ? (64 + c8) : c8;
                cp16(smem_u32(&vd[r * VSTR + c8]), vs + (size_t)(r & 63) * 128 + gc);
            }
            CP_COMMIT();
        }

        // ---- scores: 3-term ----
        float s[8][4];
#pragma unroll
        for (int nt = 0; nt < 8; nt++)
#pragma unroll
            for (int i = 0; i < 4; i++) s[nt][i] = 0.f;

#pragma unroll
        for (int seg = 0; seg < 3; seg++) {
            const uint32_t (*aa)[4] = (seg < 2) ? qh : ql;
            const int colb = (seg == 1) ? 64 : 0;
#pragma unroll
            for (int k4 = 0; k4 < 4; k4++) {
#pragma unroll
                for (int np = 0; np < 4; np++) {
                    uint32_t t[4];
                    ldsm4(t, smem_u32(&kc[(np * 16 + b_r) * QSTR + colb + k4 * 16 + b_c]));
                    mma16816(s[np * 2],     aa[k4], t);
                    mma16816(s[np * 2 + 1], aa[k4], t + 2);
                }
            }
        }

        if (kb == qb) {
            const int row0 = wid * 16 + (lane >> 2);
            const int colb = (lane & 3) * 2;
#pragma unroll
            for (int nt = 0; nt < 8; nt++) {
                const int c = nt * 8 + colb;
                if (c     > row0)     s[nt][0] = -1e30f;
                if (c + 1 > row0)     s[nt][1] = -1e30f;
                if (c     > row0 + 8) s[nt][2] = -1e30f;
                if (c + 1 > row0 + 8) s[nt][3] = -1e30f;
            }
        }

        float mx0 = -1e30f, mx1 = -1e30f;
#pragma unroll
        for (int nt = 0; nt < 8; nt++) {
            mx0 = fmaxf(mx0, fmaxf(s[nt][0], s[nt][1]));
            mx1 = fmaxf(mx1, fmaxf(s[nt][2], s[nt][3]));
        }
        mx0 = fmaxf(mx0, __shfl_xor_sync(0xffffffffu, mx0, 1));
        mx0 = fmaxf(mx0, __shfl_xor_sync(0xffffffffu, mx0, 2));
        mx1 = fmaxf(mx1, __shfl_xor_sync(0xffffffffu, mx1, 1));
        mx1 = fmaxf(mx1, __shfl_xor_sync(0xffffffffu, mx1, 2));

        const float mn0 = fmaxf(m0, mx0);
        const float mn1 = fmaxf(m1, mx1);
        const float al0 = __expf(m0 - mn0);
        const float al1 = __expf(m1 - mn1);
        m0 = mn0; m1 = mn1;

        float sum0 = 0.f, sum1 = 0.f;
#pragma unroll
        for (int nt = 0; nt < 8; nt++) {
            s[nt][0] = __expf(s[nt][0] - mn0);
            s[nt][1] = __expf(s[nt][1] - mn0);
            s[nt][2] = __expf(s[nt][2] - mn1);
            s[nt][3] = __expf(s[nt][3] - mn1);
            sum0 += s[nt][0] + s[nt][1];
            sum1 += s[nt][2] + s[nt][3];
        }
        sum0 += __shfl_xor_sync(0xffffffffu, sum0, 1);
        sum0 += __shfl_xor_sync(0xffffffffu, sum0, 2);
        sum1 += __shfl_xor_sync(0xffffffffu, sum1, 1);
        sum1 += __shfl_xor_sync(0xffffffffu, sum1, 2);
        l0 = l0 * al0 + sum0;
        l1 = l1 * al1 + sum1;

#pragma unroll
        for (int nt = 0; nt < 8; nt++) {
            o[nt][0] *= al0; o[nt][1] *= al0;
            o[nt][2] *= al1; o[nt][3] *= al1;
        }

        uint32_t ph[4][4];
#pragma unroll
        for (int k4 = 0; k4 < 4; k4++) {
#pragma unroll
            for (int half = 0; half < 2; half++) {
                const int nt = k4 * 2 + half;
#pragma unroll
                for (int rr = 0; rr < 2; rr++) {
                    ph[k4][half * 2 + rr] =
                        pack_h2(s[nt][rr * 2], s[nt][rr * 2 + 1]);
                }
            }
        }

        // O += Ph*Vhi + Ph*Vlo
#pragma unroll
        for (int seg = 0; seg < 2; seg++) {
            const int rb = seg * 64;
#pragma unroll
            for (int k4 = 0; k4 < 4; k4++) {
#pragma unroll
                for (int np = 0; np < 4; np++) {
                    uint32_t t[4];
                    ldsm4t(t, smem_u32(&vc[(rb + k4 * 16 + v_r) * VSTR + np * 16 + v_c]));
                    mma16816(o[np * 2],     ph[k4], t);
                    mma16816(o[np * 2 + 1], ph[k4], t + 2);
                }
            }
        }

        if (kb < qb) {
            CP_WAIT0();      // next tile arrived
            __syncthreads(); // visible to all; all warps done with this buf
        }
    }

    // ---- normalize, split to fp16 hi|lo, store to g_atta (K'=2048) ----
    const float i0 = 1.0f / l0;
    const float i1 = 1.0f / l1;
    const int row0 = qb * 64 + wid * 16 + (lane >> 2);
    const int colb = h * 64 + (lane & 3) * 2;
    __half* rp0 = g_atta + ((size_t)b * Ss + row0) * KP;
    __half* rp1 = g_atta + ((size_t)b * Ss + row0 + 8) * KP;
#pragma unroll
    for (int nt = 0; nt < 8; nt++) {
        const int c = colb + nt * 8;
        {
            const float v0 = o[nt][0] * i0, v1 = o[nt][1] * i0;
            __half2 hp = __floats2half2_rn(v0, v1);
            __half2 lp = __floats2half2_rn(
                v0 - __low2float(hp), v1 - __high2float(hp));
            *reinterpret_cast<uint32_t*>(rp0 + c)        = *reinterpret_cast<uint32_t*>(&hp);
            *reinterpret_cast<uint32_t*>(rp0 + 1024 + c) = *reinterpret_cast<uint32_t*>(&lp);
        }
        {
            const float v0 = o[nt][2] * i1, v1 = o[nt][3] * i1;
            __half2 hp = __floats2half2_rn(v0, v1);
            __half2 lp = __floats2half2_rn(
                v0 - __low2float(hp), v1 - __high2float(hp));
            *reinterpret_cast<uint32_t*>(rp1 + c)        = *reinterpret_cast<uint32_t*>(&hp);
            *reinterpret_cast<uint32_t*>(rp1 + 1024 + c) = *reinterpret_cast<uint32_t*>(&lp);
        }
    }
}

// ---------------------------------------------------------------------------
// kernel_launch
// Inputs: 0:x 1:mask(ignored) 2:Wq 3:bq 4:Wk 5:bk 6:Wv 7:bv 8:Wo 9:bo
// ---------------------------------------------------------------------------
extern "C" void kernel_launch(void* const* d_in, const int* in_sizes, int n_in,
                              void* d_out, int out_size)
{
    (void)in_sizes; (void)n_in; (void)out_size;
    const float* x  = (const float*)d_in[0];
    const float* Wq = (const float*)d_in[2];
    const float* bq = (const float*)d_in[3];
    const float* Wk = (const float*)d_in[4];
    const float* bk = (const float*)d_in[5];
    const float* Wv = (const float*)d_in[6];
    const float* bv = (const float*)d_in[7];
    const float* Wo = (const float*)d_in[8];
    const float* bo = (const float*)d_in[9];
    float* out = (float*)d_out;

    cudaFuncSetAttribute(attn_mma_kernel,
                         cudaFuncAttributeMaxDynamicSharedMemorySize, (int)ATT_SMEM2);
    cudaFuncSetAttribute(gemm_qkv_mma,
                         cudaFuncAttributeMaxDynamicSharedMemorySize, (int)GEMM_SMEM);
    cudaFuncSetAttribute(gemm_o_mma,
                         cudaFuncAttributeMaxDynamicSharedMemorySize, (int)GEMM_SMEM);

    split_w_kernel<<<2048, 256>>>(Wq, Wk, Wv, Wo);
    split_x_kernel<<<4096, 256>>>(x);

    dim3 qkv_grid(8, 64, 3);
    gemm_qkv_mma<<<qkv_grid, 256, GEMM_SMEM>>>(bq, bk, bv);

    dim3 attn_grid(Ss / 64, Hh, Bb);
    attn_mma_kernel<<<attn_grid, 128, ATT_SMEM2>>>();

    dim3 o_grid(8, 64, 1);
    gemm_o_mma<<<o_grid, 256, GEMM_SMEM>>>(bo, out);
}